// round 2
// baseline (speedup 1.0000x reference)
#include <cuda_runtime.h>
#include <math.h>

// Problem constants
#define BB 1024
#define LL 8
#define EE 256
#define RR 10000
#define RP1 10001
#define SPLITK 16

// ------------------------- scratch (static device memory, no runtime alloc) ----
__device__ float g_x[BB*LL*EE];            // embedded inputs (B, L, E)
__device__ float g_xw[BB*LL*4*EE];         // x @ w_ih^T + b_ih + b_hh   (B*L, 4E)
__device__ float g_hc[2*BB*EE];            // h | c
__device__ float g_G[BB*4*EE];             // LSTM gate pre-activations
__device__ float g_hid[BB*LL*EE];          // body_hid (B, L, E)
__device__ float g_embT[EE*RR];            // emb_w transposed (E, R)
__device__ float g_emb1[BB*EE];
__device__ float g_fc1[BB*EE];
__device__ float g_psf[BB*RP1];            // softmax probabilities
__device__ float g_part[SPLITK*BB*EE];     // split-K partials
__device__ float g_svec[EE];               // per-iteration fused bias for fc1
__device__ float g_bsum[4*EE];             // b_ih + b_hh

// ------------------------- generic NT SGEMM:  C[m,n] = dot(A[m,:K], B[n,:K]) --
// Epilogue: C = f(acc + bias[n] + scale[m]*add[m*addStride+n]); f = relu opt.
// splitK > 1: write raw partials to part[z*M*N + m*N + n] (reduced later).
template<int BM,int BN,int BK,int TM,int TN>
__global__ void __launch_bounds__(256) sgemm_nt(
    int M, int N, int K,
    const float* __restrict__ A, int lda,
    const float* __restrict__ Bm, int ldb,
    float* __restrict__ C, int ldc,
    const float* __restrict__ bias,
    const float* __restrict__ add, long long addStride,
    const float* __restrict__ scale, int scaleStride,
    int doRelu,
    float* __restrict__ part, int splitK)
{
    constexpr int TX = BN / TN;
    constexpr int TY = BM / TM;
    constexpr int THREADS = TX * TY;
    static_assert(THREADS == 256, "thread count");

    __shared__ float As[BK][BM];
    __shared__ float Bs[BK][BN];

    const int tid = threadIdx.x;
    const int tx = tid % TX;
    const int ty = tid / TX;
    const int row0 = blockIdx.y * BM;
    const int col0 = blockIdx.x * BN;

    int k0 = 0, k1 = K;
    if (splitK > 1) {
        int kc = (K + splitK - 1) / splitK;
        k0 = blockIdx.z * kc;
        k1 = min(K, k0 + kc);
    }

    float acc[TM][TN];
#pragma unroll
    for (int i = 0; i < TM; i++)
#pragma unroll
        for (int j = 0; j < TN; j++) acc[i][j] = 0.f;

    for (int kk = k0; kk < k1; kk += BK) {
#pragma unroll
        for (int t = tid; t < BM * BK; t += THREADS) {
            int m = t / BK, k = t % BK;
            int gm = row0 + m, gk = kk + k;
            As[k][m] = (gm < M && gk < k1) ? A[(long long)gm * lda + gk] : 0.f;
        }
#pragma unroll
        for (int t = tid; t < BN * BK; t += THREADS) {
            int n = t / BK, k = t % BK;
            int gn = col0 + n, gk = kk + k;
            Bs[k][n] = (gn < N && gk < k1) ? Bm[(long long)gn * ldb + gk] : 0.f;
        }
        __syncthreads();

#pragma unroll
        for (int k = 0; k < BK; k++) {
            float a[TM], b[TN];
#pragma unroll
            for (int i4 = 0; i4 < TM / 4; i4++) {
                float4 v = *(const float4*)&As[k][ty * TM + i4 * 4];
                a[4*i4+0] = v.x; a[4*i4+1] = v.y; a[4*i4+2] = v.z; a[4*i4+3] = v.w;
            }
#pragma unroll
            for (int j4 = 0; j4 < TN / 4; j4++) {
                float4 v = *(const float4*)&Bs[k][tx * TN + j4 * 4];
                b[4*j4+0] = v.x; b[4*j4+1] = v.y; b[4*j4+2] = v.z; b[4*j4+3] = v.w;
            }
#pragma unroll
            for (int i = 0; i < TM; i++)
#pragma unroll
                for (int j = 0; j < TN; j++) acc[i][j] += a[i] * b[j];
        }
        __syncthreads();
    }

    if (splitK > 1) {
        float* P = part + (long long)blockIdx.z * M * N;
#pragma unroll
        for (int i = 0; i < TM; i++) {
            int m = row0 + ty * TM + i;
            if (m >= M) continue;
#pragma unroll
            for (int j = 0; j < TN; j++) {
                int n = col0 + tx * TN + j;
                if (n >= N) continue;
                P[(long long)m * N + n] = acc[i][j];
            }
        }
        return;
    }

#pragma unroll
    for (int i = 0; i < TM; i++) {
        int m = row0 + ty * TM + i;
        if (m >= M) continue;
        float sc = scale ? scale[(long long)m * scaleStride] : 1.f;
#pragma unroll
        for (int j = 0; j < TN; j++) {
            int n = col0 + tx * TN + j;
            if (n >= N) continue;
            float v = acc[i][j];
            if (bias) v += bias[n];
            if (add)  v += sc * add[(long long)m * addStride + n];
            if (doRelu) v = fmaxf(v, 0.f);
            C[(long long)m * ldc + n] = v;
        }
    }
}

// ------------------------- split-K reduction + epilogue ------------------------
__global__ void reduce_splitk(int M, int N, int S,
    const float* __restrict__ part, float* __restrict__ C, int ldc,
    const float* __restrict__ bias,
    const float* __restrict__ add, long long addStride,
    const float* __restrict__ scale, int scaleStride, int doRelu)
{
    long long idx = (long long)blockIdx.x * blockDim.x + threadIdx.x;
    if (idx >= (long long)M * N) return;
    int m = (int)(idx / N), n = (int)(idx % N);
    float v = 0.f;
    for (int s = 0; s < S; s++) v += part[(long long)s * M * N + idx];
    if (bias) v += bias[n];
    if (add) {
        float sc = scale ? scale[(long long)m * scaleStride] : 1.f;
        v += sc * add[(long long)m * addStride + n];
    }
    if (doRelu) v = fmaxf(v, 0.f);
    C[(long long)m * ldc + n] = v;
}

// ------------------------- small helper kernels --------------------------------
__global__ void transpose_kernel(const float* __restrict__ src, float* __restrict__ dst)
{
    __shared__ float tile[32][33];
    int r0 = blockIdx.x * 32, e0 = blockIdx.y * 32;
    for (int i = threadIdx.y; i < 32; i += 8) {
        int r = r0 + i, e = e0 + threadIdx.x;
        tile[i][threadIdx.x] = (r < RR) ? src[(long long)r * EE + e] : 0.f;
    }
    __syncthreads();
    for (int i = threadIdx.y; i < 32; i += 8) {
        int e = e0 + i, r = r0 + threadIdx.x;
        if (r < RR) dst[(long long)e * RR + r] = tile[threadIdx.x][i];
    }
}

__global__ void gather_kernel(const int* __restrict__ bodys,
                              const float* __restrict__ emb_w, float* __restrict__ x)
{
    int bl = blockIdx.x;                 // B*L rows
    int r = bodys[bl];
    const float4* src = (const float4*)(emb_w + (long long)r * EE);
    float4* dst = (float4*)(x + (long long)bl * EE);
    for (int i = threadIdx.x; i < EE / 4; i += blockDim.x) dst[i] = src[i];
}

__global__ void bsum_kernel(const float* __restrict__ b_ih,
                            const float* __restrict__ b_hh, float* __restrict__ bsum)
{
    int i = threadIdx.x;
    if (i < 4 * EE) bsum[i] = b_ih[i] + b_hh[i];
}

__global__ void zero_kernel(float* __restrict__ p, int n)
{
    int i = blockIdx.x * blockDim.x + threadIdx.x;
    if (i < n) p[i] = 0.f;
}

__global__ void lstm_gates(const float* __restrict__ G, float* __restrict__ h,
                           float* __restrict__ c, float* __restrict__ hid, int t)
{
    int idx = blockIdx.x * blockDim.x + threadIdx.x;
    if (idx >= BB * EE) return;
    int b = idx >> 8, e = idx & 255;
    const float* g = G + (long long)b * (4 * EE);
    float gi = g[e], gf = g[EE + e], gg = g[2 * EE + e], go = g[3 * EE + e];
    float si = 1.f / (1.f + __expf(-gi));
    float sf = 1.f / (1.f + __expf(-gf));
    float so = 1.f / (1.f + __expf(-go));
    float cn = sf * c[idx] + si * tanhf(gg);
    c[idx] = cn;
    float hn = so * tanhf(cn);
    h[idx] = hn;
    hid[((long long)b * LL + t) * EE + e] = hn;
}

__global__ void softmax_kernel(const float* __restrict__ prob, float* __restrict__ psf)
{
    int b = blockIdx.x, tid = threadIdx.x;
    const float* x = prob + (long long)b * RP1;
    float* y = psf + (long long)b * RP1;
    __shared__ float red[8];

    float mx = -1e30f;
    for (int i = tid; i < RP1; i += 256) mx = fmaxf(mx, x[i]);
    for (int o = 16; o; o >>= 1) mx = fmaxf(mx, __shfl_xor_sync(0xffffffffu, mx, o));
    if ((tid & 31) == 0) red[tid >> 5] = mx;
    __syncthreads();
    mx = red[0];
#pragma unroll
    for (int w = 1; w < 8; w++) mx = fmaxf(mx, red[w]);

    float s = 0.f;
    for (int i = tid; i < RP1; i += 256) s += __expf(x[i] - mx);
    for (int o = 16; o; o >>= 1) s += __shfl_xor_sync(0xffffffffu, s, o);
    __syncthreads();
    if ((tid & 31) == 0) red[tid >> 5] = s;
    __syncthreads();
    s = 0.f;
#pragma unroll
    for (int w = 0; w < 8; w++) s += red[w];
    float inv = 1.f / s;
    for (int i = tid; i < RP1; i += 256) y[i] = __expf(x[i] - mx) * inv;
}

// svec[e] = fc1_b[e] + dot(fc1_w[e, 256:512], emb_w[iter+1, :])
__global__ void svec_kernel(const float* __restrict__ fc1_w, const float* __restrict__ fc1_b,
                            const float* __restrict__ emb_w, int iter, float* __restrict__ svec)
{
    __shared__ float er[EE];
    int e = threadIdx.x;
    er[e] = emb_w[(long long)(iter + 1) * EE + e];
    __syncthreads();
    const float* w = fc1_w + (long long)e * (2 * EE) + EE;
    float s = fc1_b[e];
#pragma unroll 8
    for (int k = 0; k < EE; k++) s += w[k] * er[k];
    svec[e] = s;
}

__global__ void concat_kernel(const float* __restrict__ emb1,
                              const float* __restrict__ emb_w, float* __restrict__ out)
{
    int idx = blockIdx.x * blockDim.x + threadIdx.x;
    if (idx >= BB * 2 * EE) return;
    int b = idx >> 9, e = idx & 511;
    out[idx] = (e < EE) ? emb1[(long long)b * EE + e]
                        : emb_w[(long long)(LL - 1) * EE + (e - EE)];
}

// ------------------------- host launch sequence --------------------------------
static float* sym_addr(const void* s) { void* p = nullptr; cudaGetSymbolAddress(&p, s); return (float*)p; }

extern "C" void kernel_launch(void* const* d_in, const int* in_sizes, int n_in,
                              void* d_out, int out_size)
{
    const int*   bodys = (const int*)d_in[0];
    const float* emb_w = (const float*)d_in[1];
    const float* w_ih  = (const float*)d_in[2];
    const float* w_hh  = (const float*)d_in[3];
    const float* b_ih  = (const float*)d_in[4];
    const float* b_hh  = (const float*)d_in[5];
    const float* fc1_w = (const float*)d_in[6];
    const float* fc1_b = (const float*)d_in[7];
    const float* fc2_w = (const float*)d_in[8];
    const float* fc2_b = (const float*)d_in[9];

    float* prob   = (float*)d_out;                       // (B, R+1)
    float* outcat = prob + (long long)BB * RP1;          // (B, 2E)

    float* x    = sym_addr(g_x);
    float* xw   = sym_addr(g_xw);
    float* hc   = sym_addr(g_hc);
    float* h    = hc;
    float* c    = hc + BB * EE;
    float* G    = sym_addr(g_G);
    float* hid  = sym_addr(g_hid);
    float* embT = sym_addr(g_embT);
    float* emb1 = sym_addr(g_emb1);
    float* fc1o = sym_addr(g_fc1);
    float* psf  = sym_addr(g_psf);
    float* part = sym_addr(g_part);
    float* svec = sym_addr(g_svec);
    float* bsum = sym_addr(g_bsum);

    // Prologue
    transpose_kernel<<<dim3((RR + 31) / 32, EE / 32), dim3(32, 8)>>>(emb_w, embT);
    gather_kernel<<<BB * LL, 64>>>(bodys, emb_w, x);
    bsum_kernel<<<1, 4 * EE>>>(b_ih, b_hh, bsum);
    zero_kernel<<<(2 * BB * EE + 255) / 256, 256>>>(hc, 2 * BB * EE);

    // xW = x @ w_ih^T + (b_ih + b_hh)   : (8192, 1024), K=256
    sgemm_nt<128,128,8,8,8><<<dim3((4*EE)/128, (BB*LL)/128), 256>>>(
        BB*LL, 4*EE, EE, x, EE, w_ih, EE, xw, 4*EE,
        bsum, (const float*)nullptr, 0, (const float*)nullptr, 0, 0,
        (float*)nullptr, 1);

    // LSTM: 8 sequential steps
    for (int t = 0; t < LL; t++) {
        // G = h @ w_hh^T + xW[:, t]   : (1024, 1024), K=256
        sgemm_nt<128,64,8,8,4><<<dim3((4*EE)/64, BB/128), 256>>>(
            BB, 4*EE, EE, h, EE, w_hh, EE, G, 4*EE,
            (const float*)nullptr, xw + (long long)t * (4*EE), (long long)LL * 4 * EE,
            (const float*)nullptr, 0, 0, (float*)nullptr, 1);
        lstm_gates<<<(BB*EE + 255) / 256, 256>>>(G, h, c, hid, t);
    }

    // ---------- iteration 0: emb_concat = [x[:,0,:], x[:,1,:]] (contiguous rows)
    sgemm_nt<64,64,16,4,4><<<dim3(EE/64, BB/64), 256>>>(
        BB, EE, 2*EE, x, LL*EE, fc1_w, 2*EE, fc1o, EE,
        fc1_b, (const float*)nullptr, 0, (const float*)nullptr, 0, 1,
        (float*)nullptr, 1);
    sgemm_nt<128,128,8,8,8><<<dim3((RP1 + 127) / 128, BB/128), 256>>>(
        BB, RP1, EE, fc1o, EE, fc2_w, EE, prob, RP1,
        fc2_b, (const float*)nullptr, 0, (const float*)nullptr, 0, 0,
        (float*)nullptr, 1);
    softmax_kernel<<<BB, 256>>>(prob, psf);

    // ---------- iterations 1..6
    for (int i = 1; i < LL - 1; i++) {
        svec_kernel<<<1, EE>>>(fc1_w, fc1_b, emb_w, i, svec);

        // emb_1 partials: P[:, :R] @ emb_w  -> split-K over K=10000
        sgemm_nt<128,128,8,8,8><<<dim3(EE/128, BB/128, SPLITK), 256>>>(
            BB, EE, RR, psf, RP1, embT, RR, (float*)nullptr, 0,
            (const float*)nullptr, (const float*)nullptr, 0,
            (const float*)nullptr, 0, 0, part, SPLITK);
        // reduce + add last-prob * body_hid[:, i, :]
        reduce_splitk<<<(BB*EE + 255) / 256, 256>>>(
            BB, EE, SPLITK, part, emb1, EE,
            (const float*)nullptr, hid + (long long)i * EE, (long long)LL * EE,
            psf + RR, RP1, 0);

        // fc1: relu(emb_1 @ W1a^T + svec)   (svec folds second-half + fc1_b)
        sgemm_nt<64,64,16,4,4><<<dim3(EE/64, BB/64), 256>>>(
            BB, EE, EE, emb1, EE, fc1_w, 2*EE, fc1o, EE,
            svec, (const float*)nullptr, 0, (const float*)nullptr, 0, 1,
            (float*)nullptr, 1);

        // fc2 -> prob (written straight into d_out)
        sgemm_nt<128,128,8,8,8><<<dim3((RP1 + 127) / 128, BB/128), 256>>>(
            BB, RP1, EE, fc1o, EE, fc2_w, EE, prob, RP1,
            fc2_b, (const float*)nullptr, 0, (const float*)nullptr, 0, 0,
            (float*)nullptr, 1);

        if (i < LL - 2) softmax_kernel<<<BB, 256>>>(prob, psf);
    }

    // emb_concat output = [emb_1, emb_w[7]]
    if (out_size >= BB * RP1 + BB * 2 * EE)
        concat_kernel<<<(BB * 2 * EE + 255) / 256, 256>>>(emb1, emb_w, outcat);
}

// round 4
// speedup vs baseline: 2.4772x; 2.4772x over previous
#include <cuda_runtime.h>
#include <cuda_bf16.h>
#include <math.h>
#include <stdint.h>

// Problem constants
#define BB 1024
#define LL 8
#define EE 256
#define RR 10000
#define RP1 10001
#define RS 10016            // padded K stride for psf/embT (mult of 32)
#define NSPLIT 8
#define KCH 1280            // split-K chunk (mult of 32)

// ------------------------- scratch (static device memory) ---------------------
__device__ float g_xw[BB*LL*4*EE];
__device__ float g_c[BB*EE];
__device__ float g_G[BB*4*EE];
__device__ float g_hid[BB*LL*EE];
__device__ float g_emb1[BB*EE];
__device__ float g_part[NSPLIT*BB*EE];
__device__ float g_svec[EE];
__device__ float g_bsum[4*EE];
__device__ float g_plast[BB];

__device__ __nv_bfloat16 g_xh[BB*LL*EE],  g_xl[BB*LL*EE];
__device__ __nv_bfloat16 g_hh[BB*EE],     g_hl[BB*EE];
__device__ __nv_bfloat16 g_wihh[4*EE*EE], g_wihl[4*EE*EE];
__device__ __nv_bfloat16 g_whhh[4*EE*EE], g_whhl[4*EE*EE];
__device__ __nv_bfloat16 g_fc1wh[EE*2*EE],g_fc1wl[EE*2*EE];
__device__ __nv_bfloat16 g_fc2wh[(long long)RP1*EE], g_fc2wl[(long long)RP1*EE];
__device__ __nv_bfloat16 g_embTh[(long long)EE*RS],  g_embTl[(long long)EE*RS];
__device__ __nv_bfloat16 g_psfh[(long long)BB*RS],   g_psfl[(long long)BB*RS];
__device__ __nv_bfloat16 g_fc1h[BB*EE],   g_fc1l[BB*EE];
__device__ __nv_bfloat16 g_e1h[BB*EE],    g_e1l[BB*EE];

// ------------------------- PTX helpers ----------------------------------------
__device__ __forceinline__ uint32_t u32s(const void* p){
    uint32_t a;
    asm("{ .reg .u64 t; cvta.to.shared.u64 t, %1; cvt.u32.u64 %0, t; }" : "=r"(a) : "l"(p));
    return a;
}
__device__ __forceinline__ void cpa16(uint32_t dst, const void* src, uint32_t sz){
    asm volatile("cp.async.cg.shared.global [%0], [%1], 16, %2;" :: "r"(dst), "l"(src), "r"(sz));
}
__device__ __forceinline__ void cpa_commit(){ asm volatile("cp.async.commit_group;" ::: "memory"); }
__device__ __forceinline__ void ldm4(uint32_t* r, uint32_t addr){
    asm volatile("ldmatrix.sync.aligned.m8n8.x4.shared.b16 {%0,%1,%2,%3}, [%4];"
        : "=r"(r[0]), "=r"(r[1]), "=r"(r[2]), "=r"(r[3]) : "r"(addr));
}
__device__ __forceinline__ void mma_bf16(float* c, const uint32_t* a, const uint32_t* b){
    asm volatile(
        "mma.sync.aligned.m16n8k16.row.col.f32.bf16.bf16.f32 "
        "{%0,%1,%2,%3}, {%4,%5,%6,%7}, {%8,%9}, {%0,%1,%2,%3};"
        : "+f"(c[0]), "+f"(c[1]), "+f"(c[2]), "+f"(c[3])
        : "r"(a[0]), "r"(a[1]), "r"(a[2]), "r"(a[3]), "r"(b[0]), "r"(b[1]));
}
__device__ __forceinline__ void split2(float v, __nv_bfloat16& hi, __nv_bfloat16& lo){
    hi = __float2bfloat16(v);
    lo = __float2bfloat16(v - __bfloat162float(hi));
}

// ------------------------- bf16x3 NT GEMM --------------------------------------
// C[m,n] = sum_k A[m,k]*B[n,k], A/B pre-split into hi/lo bf16.
// BM=BN=128, BK=32, 256 threads, 4-stage cp.async pipeline.
// Tiles in SMEM: rows padded to 80B (40 bf16) -> conflict-free ldmatrix.
#define ST 4
#define TILEB 10240
#define STAGEB (4*TILEB)
#define GSMEM (ST*STAGEB)

__global__ void __launch_bounds__(256,1) tgemm(
    int M, int N, int K,
    const __nv_bfloat16* __restrict__ Ah, const __nv_bfloat16* __restrict__ Al, int lda,
    const __nv_bfloat16* __restrict__ Bh, const __nv_bfloat16* __restrict__ Bl, int ldb,
    float* __restrict__ C, int ldc,
    const float* __restrict__ bias,
    const float* __restrict__ add, long long addStride,
    int doRelu,
    __nv_bfloat16* __restrict__ Oh, __nv_bfloat16* __restrict__ Ol, int ldo,
    float* __restrict__ part, int kChunk)
{
    extern __shared__ char smem[];
    const int tid = threadIdx.x, lane = tid & 31, wid = tid >> 5;
    const int wm = wid >> 2, wn = wid & 3;      // 2 (m) x 4 (n) warps
    const int m0 = blockIdx.y * 128, n0 = blockIdx.x * 128;

    int k0 = 0, k1 = K;
    if (part){ k0 = blockIdx.z * kChunk; k1 = min(K, k0 + kChunk); }
    const int nch = (k1 - k0) >> 5;             // K always multiple of 32 here

    const uint32_t sb = u32s(smem);

    // per-thread loader coords: 512 (row,chunk) slots per tile, 2 iters
    auto load = [&](int c){
        if (c < nch){
            uint32_t st = sb + (uint32_t)(c & (ST-1)) * STAGEB;
            int kk = k0 + c * 32;
            #pragma unroll
            for (int it = 0; it < 2; it++){
                int idx = tid + it * 256;
                int row = idx >> 2, ch = idx & 3;
                uint32_t d = st + (uint32_t)row * 80 + (uint32_t)ch * 16;
                int off = kk + ch * 8;
                {   // A hi/lo
                    int gm = m0 + row;
                    uint32_t sz = (gm < M) ? 16u : 0u;
                    long long o = (long long)(gm < M ? gm : 0) * lda + off;
                    cpa16(d,          Ah + o, sz);
                    cpa16(d + TILEB,  Al + o, sz);
                }
                {   // B hi/lo
                    int gn = n0 + row;
                    uint32_t sz = (gn < N) ? 16u : 0u;
                    long long o = (long long)(gn < N ? gn : 0) * ldb + off;
                    cpa16(d + 2*TILEB, Bh + o, sz);
                    cpa16(d + 3*TILEB, Bl + o, sz);
                }
            }
        }
        cpa_commit();
    };

    // fragment smem offsets (bytes)
    const int aq = lane >> 3, ar = lane & 7;
    const uint32_t aoff = (uint32_t)((wm*64 + (aq&1)*8 + ar) * 80 + (aq>>1) * 16);
    const uint32_t boff = (uint32_t)((wn*32 + ((lane>>4)&1)*8 + ar) * 80 + ((lane>>3)&1) * 16);

    float acc[4][4][4];
    #pragma unroll
    for (int i = 0; i < 4; i++)
        #pragma unroll
        for (int j = 0; j < 4; j++)
            #pragma unroll
            for (int q = 0; q < 4; q++) acc[i][j][q] = 0.f;

    for (int c = 0; c < ST-1; c++) load(c);

    for (int c = 0; c < nch; c++){
        asm volatile("cp.async.wait_group %0;" :: "n"(ST-2) : "memory");
        __syncthreads();
        load(c + ST - 1);

        uint32_t st = sb + (uint32_t)(c & (ST-1)) * STAGEB;
        #pragma unroll
        for (int ks = 0; ks < 2; ks++){
            uint32_t Ahr[4][4], Alr[4][4], Bhr[4][2], Blr[4][2];
            #pragma unroll
            for (int i = 0; i < 4; i++){
                ldm4(Ahr[i], st + aoff + i*1280 + ks*32);
                ldm4(Alr[i], st + TILEB + aoff + i*1280 + ks*32);
            }
            #pragma unroll
            for (int p = 0; p < 2; p++){
                uint32_t t[4];
                ldm4(t, st + 2*TILEB + boff + p*1280 + ks*32);
                Bhr[2*p][0]=t[0]; Bhr[2*p][1]=t[1]; Bhr[2*p+1][0]=t[2]; Bhr[2*p+1][1]=t[3];
                ldm4(t, st + 3*TILEB + boff + p*1280 + ks*32);
                Blr[2*p][0]=t[0]; Blr[2*p][1]=t[1]; Blr[2*p+1][0]=t[2]; Blr[2*p+1][1]=t[3];
            }
            #pragma unroll
            for (int i = 0; i < 4; i++)
                #pragma unroll
                for (int j = 0; j < 4; j++){
                    mma_bf16(acc[i][j], Ahr[i], Bhr[j]);
                    mma_bf16(acc[i][j], Ahr[i], Blr[j]);
                    mma_bf16(acc[i][j], Alr[i], Bhr[j]);
                }
        }
    }

    // epilogue
    const int mr = m0 + wm*64 + (lane >> 2);
    const int nc0 = n0 + wn*32 + (lane & 3)*2;

    if (part){
        float* P = part + (long long)blockIdx.z * M * N;
        #pragma unroll
        for (int i = 0; i < 4; i++)
            #pragma unroll
            for (int j = 0; j < 4; j++)
                #pragma unroll
                for (int h = 0; h < 2; h++){
                    int m = mr + i*16 + h*8, n = nc0 + j*8;
                    P[(long long)m*N + n]     = acc[i][j][2*h];
                    P[(long long)m*N + n + 1] = acc[i][j][2*h+1];
                }
        return;
    }

    #pragma unroll
    for (int i = 0; i < 4; i++)
        #pragma unroll
        for (int j = 0; j < 4; j++)
            #pragma unroll
            for (int h = 0; h < 2; h++){
                int m = mr + i*16 + h*8;
                #pragma unroll
                for (int e = 0; e < 2; e++){
                    int n = nc0 + j*8 + e;
                    if (n >= N) continue;
                    float v = acc[i][j][2*h + e];
                    if (bias) v += bias[n];
                    if (add)  v += add[(long long)m*addStride + n];
                    if (doRelu) v = fmaxf(v, 0.f);
                    if (C) C[(long long)m*ldc + n] = v;
                    if (Oh){
                        __nv_bfloat16 hi, lo; split2(v, hi, lo);
                        Oh[(long long)m*ldo + n] = hi;
                        Ol[(long long)m*ldo + n] = lo;
                    }
                }
            }
}

// ------------------------- split-K reduce + emb1 epilogue ----------------------
__global__ void reduce_splitk(const float* __restrict__ part, float* __restrict__ emb1,
                              __nv_bfloat16* __restrict__ eh, __nv_bfloat16* __restrict__ el,
                              const float* __restrict__ hidI, const float* __restrict__ plast)
{
    int idx = blockIdx.x * blockDim.x + threadIdx.x;
    if (idx >= BB * EE) return;
    int m = idx >> 8, n = idx & 255;
    float v = 0.f;
    #pragma unroll
    for (int s = 0; s < NSPLIT; s++) v += part[(long long)s * BB * EE + idx];
    v += plast[m] * hidI[(long long)m * LL * EE + n];
    emb1[idx] = v;
    __nv_bfloat16 hi, lo; split2(v, hi, lo);
    eh[idx] = hi; el[idx] = lo;
}

// ------------------------- helper kernels --------------------------------------
__global__ void conv_kernel(const float* __restrict__ src, __nv_bfloat16* __restrict__ hi,
                            __nv_bfloat16* __restrict__ lo, int n)
{
    int i = blockIdx.x * blockDim.x + threadIdx.x;
    if (i < n){ __nv_bfloat16 h, l; split2(src[i], h, l); hi[i] = h; lo[i] = l; }
}

__global__ void transpose_kernel(const float* __restrict__ src,
                                 __nv_bfloat16* __restrict__ dh, __nv_bfloat16* __restrict__ dl)
{
    __shared__ float tile[32][33];
    int r0 = blockIdx.x * 32, e0 = blockIdx.y * 32;
    for (int i = threadIdx.y; i < 32; i += 8){
        int r = r0 + i, e = e0 + threadIdx.x;
        tile[i][threadIdx.x] = (r < RR) ? src[(long long)r * EE + e] : 0.f;
    }
    __syncthreads();
    for (int i = threadIdx.y; i < 32; i += 8){
        int e = e0 + i, r = r0 + threadIdx.x;       // r < RS by grid
        __nv_bfloat16 h, l; split2(tile[threadIdx.x][i], h, l);
        dh[(long long)e * RS + r] = h;
        dl[(long long)e * RS + r] = l;
    }
}

__global__ void gather_kernel(const int* __restrict__ bodys, const float* __restrict__ emb_w,
                              __nv_bfloat16* __restrict__ xh, __nv_bfloat16* __restrict__ xl)
{
    int bl = blockIdx.x;
    int r = bodys[bl];
    for (int i = threadIdx.x; i < EE; i += blockDim.x){
        __nv_bfloat16 h, l; split2(emb_w[(long long)r * EE + i], h, l);
        xh[(long long)bl * EE + i] = h;
        xl[(long long)bl * EE + i] = l;
    }
}

__global__ void bsum_kernel(const float* __restrict__ b_ih, const float* __restrict__ b_hh,
                            float* __restrict__ bsum)
{
    int i = threadIdx.x;
    if (i < 4 * EE) bsum[i] = b_ih[i] + b_hh[i];
}

__global__ void zinit_kernel(__nv_bfloat16* __restrict__ hh, __nv_bfloat16* __restrict__ hl,
                             float* __restrict__ c)
{
    int i = blockIdx.x * blockDim.x + threadIdx.x;
    if (i < BB * EE){ hh[i] = __float2bfloat16(0.f); hl[i] = __float2bfloat16(0.f); c[i] = 0.f; }
}

__global__ void lstm_gates(const float* __restrict__ G, __nv_bfloat16* __restrict__ hh,
                           __nv_bfloat16* __restrict__ hl, float* __restrict__ c,
                           float* __restrict__ hid, int t)
{
    int idx = blockIdx.x * blockDim.x + threadIdx.x;
    if (idx >= BB * EE) return;
    int b = idx >> 8, e = idx & 255;
    const float* g = G + (long long)b * (4 * EE);
    float gi = g[e], gf = g[EE + e], gg = g[2*EE + e], go = g[3*EE + e];
    float si = 1.f / (1.f + __expf(-gi));
    float sf = 1.f / (1.f + __expf(-gf));
    float so = 1.f / (1.f + __expf(-go));
    float cn = sf * c[idx] + si * tanhf(gg);
    c[idx] = cn;
    float hn = so * tanhf(cn);
    __nv_bfloat16 hi, lo; split2(hn, hi, lo);
    hh[idx] = hi; hl[idx] = lo;
    hid[((long long)b * LL + t) * EE + e] = hn;
}

// softmax: prob (stride RP1) -> psf hi/lo (stride RS, col RR.. zeroed), plast[b]
__global__ void __launch_bounds__(256) softmax_kernel(
    const float* __restrict__ prob, __nv_bfloat16* __restrict__ ph,
    __nv_bfloat16* __restrict__ pl, float* __restrict__ plast)
{
    int b = blockIdx.x, tid = threadIdx.x;
    const float* x = prob + (long long)b * RP1;
    __shared__ float red[8];

    float v[40]; int cnt = 0;
    float mx = -1e30f;
    for (int i = tid; i < RP1; i += 256){ float t = x[i]; v[cnt++] = t; mx = fmaxf(mx, t); }
    for (int o = 16; o; o >>= 1) mx = fmaxf(mx, __shfl_xor_sync(0xffffffffu, mx, o));
    if ((tid & 31) == 0) red[tid >> 5] = mx;
    __syncthreads();
    mx = red[0];
    #pragma unroll
    for (int w = 1; w < 8; w++) mx = fmaxf(mx, red[w]);

    float s = 0.f;
    for (int j = 0; j < cnt; j++){ v[j] = __expf(v[j] - mx); s += v[j]; }
    for (int o = 16; o; o >>= 1) s += __shfl_xor_sync(0xffffffffu, s, o);
    __syncthreads();
    if ((tid & 31) == 0) red[tid >> 5] = s;
    __syncthreads();
    s = 0.f;
    #pragma unroll
    for (int w = 0; w < 8; w++) s += red[w];
    float inv = 1.f / s;

    __nv_bfloat16* yh = ph + (long long)b * RS;
    __nv_bfloat16* yl = pl + (long long)b * RS;
    int j = 0;
    for (int i = tid; i < RS; i += 256){
        float t = 0.f;
        if (i < RP1){ t = v[j++] * inv; }
        if (i < RR){
            __nv_bfloat16 hi, lo; split2(t, hi, lo);
            yh[i] = hi; yl[i] = lo;
        } else {
            if (i == RR) plast[b] = t;
            yh[i] = __float2bfloat16(0.f);
            yl[i] = __float2bfloat16(0.f);
        }
    }
}

__global__ void svec_kernel(const float* __restrict__ fc1_w, const float* __restrict__ fc1_b,
                            const float* __restrict__ emb_w, int iter, float* __restrict__ svec)
{
    __shared__ float er[EE];
    int e = threadIdx.x;
    er[e] = emb_w[(long long)(iter + 1) * EE + e];
    __syncthreads();
    const float* w = fc1_w + (long long)e * (2 * EE) + EE;
    float s = fc1_b[e];
    #pragma unroll 8
    for (int k = 0; k < EE; k++) s += w[k] * er[k];
    svec[e] = s;
}

__global__ void concat_kernel(const float* __restrict__ emb1,
                              const float* __restrict__ emb_w, float* __restrict__ out)
{
    int idx = blockIdx.x * blockDim.x + threadIdx.x;
    if (idx >= BB * 2 * EE) return;
    int b = idx >> 9, e = idx & 511;
    out[idx] = (e < EE) ? emb1[(long long)b * EE + e]
                        : emb_w[(long long)(LL - 1) * EE + (e - EE)];
}

// ------------------------- host launch sequence --------------------------------
template<class T> static T* sym_addr(const void* s){ void* p = nullptr; cudaGetSymbolAddress(&p, s); return (T*)p; }

extern "C" void kernel_launch(void* const* d_in, const int* in_sizes, int n_in,
                              void* d_out, int out_size)
{
    const int*   bodys = (const int*)d_in[0];
    const float* emb_w = (const float*)d_in[1];
    const float* w_ih  = (const float*)d_in[2];
    const float* w_hh  = (const float*)d_in[3];
    const float* b_ih  = (const float*)d_in[4];
    const float* b_hh  = (const float*)d_in[5];
    const float* fc1_w = (const float*)d_in[6];
    const float* fc1_b = (const float*)d_in[7];
    const float* fc2_w = (const float*)d_in[8];
    const float* fc2_b = (const float*)d_in[9];

    float* prob   = (float*)d_out;
    float* outcat = prob + (long long)BB * RP1;

    float* xw    = sym_addr<float>(g_xw);
    float* cbuf  = sym_addr<float>(g_c);
    float* G     = sym_addr<float>(g_G);
    float* hid   = sym_addr<float>(g_hid);
    float* emb1  = sym_addr<float>(g_emb1);
    float* part  = sym_addr<float>(g_part);
    float* svec  = sym_addr<float>(g_svec);
    float* bsum  = sym_addr<float>(g_bsum);
    float* plast = sym_addr<float>(g_plast);

    __nv_bfloat16* xh    = sym_addr<__nv_bfloat16>(g_xh);
    __nv_bfloat16* xl    = sym_addr<__nv_bfloat16>(g_xl);
    __nv_bfloat16* hh    = sym_addr<__nv_bfloat16>(g_hh);
    __nv_bfloat16* hl    = sym_addr<__nv_bfloat16>(g_hl);
    __nv_bfloat16* wihh  = sym_addr<__nv_bfloat16>(g_wihh);
    __nv_bfloat16* wihl  = sym_addr<__nv_bfloat16>(g_wihl);
    __nv_bfloat16* whhh  = sym_addr<__nv_bfloat16>(g_whhh);
    __nv_bfloat16* whhl  = sym_addr<__nv_bfloat16>(g_whhl);
    __nv_bfloat16* fc1wh = sym_addr<__nv_bfloat16>(g_fc1wh);
    __nv_bfloat16* fc1wl = sym_addr<__nv_bfloat16>(g_fc1wl);
    __nv_bfloat16* fc2wh = sym_addr<__nv_bfloat16>(g_fc2wh);
    __nv_bfloat16* fc2wl = sym_addr<__nv_bfloat16>(g_fc2wl);
    __nv_bfloat16* embTh = sym_addr<__nv_bfloat16>(g_embTh);
    __nv_bfloat16* embTl = sym_addr<__nv_bfloat16>(g_embTl);
    __nv_bfloat16* psfh  = sym_addr<__nv_bfloat16>(g_psfh);
    __nv_bfloat16* psfl  = sym_addr<__nv_bfloat16>(g_psfl);
    __nv_bfloat16* fc1h  = sym_addr<__nv_bfloat16>(g_fc1h);
    __nv_bfloat16* fc1l  = sym_addr<__nv_bfloat16>(g_fc1l);
    __nv_bfloat16* e1h   = sym_addr<__nv_bfloat16>(g_e1h);
    __nv_bfloat16* e1l   = sym_addr<__nv_bfloat16>(g_e1l);

    cudaFuncSetAttribute(tgemm, cudaFuncAttributeMaxDynamicSharedMemorySize, GSMEM);

    // ---- prologue: weight/operand splits
    conv_kernel<<<(4*EE*EE + 255)/256, 256>>>(w_ih,  wihh,  wihl,  4*EE*EE);
    conv_kernel<<<(4*EE*EE + 255)/256, 256>>>(w_hh,  whhh,  whhl,  4*EE*EE);
    conv_kernel<<<(EE*2*EE + 255)/256, 256>>>(fc1_w, fc1wh, fc1wl, EE*2*EE);
    conv_kernel<<<(RP1*EE + 255)/256, 256>>>(fc2_w, fc2wh, fc2wl, RP1*EE);
    transpose_kernel<<<dim3(RS/32, EE/32), dim3(32, 8)>>>(emb_w, embTh, embTl);
    gather_kernel<<<BB*LL, 64>>>(bodys, emb_w, xh, xl);
    bsum_kernel<<<1, 4*EE>>>(b_ih, b_hh, bsum);
    zinit_kernel<<<(BB*EE + 255)/256, 256>>>(hh, hl, cbuf);

    // xW = x @ w_ih^T + (b_ih+b_hh) : M=8192, N=1024, K=256
    tgemm<<<dim3(8, 64), 256, GSMEM>>>(
        BB*LL, 4*EE, EE, xh, xl, EE, wihh, wihl, EE,
        xw, 4*EE, bsum, (const float*)nullptr, 0, 0,
        (__nv_bfloat16*)nullptr, (__nv_bfloat16*)nullptr, 0, (float*)nullptr, 0);

    // LSTM: 8 steps; G = h @ w_hh^T + xW[:, t]
    for (int t = 0; t < LL; t++){
        tgemm<<<dim3(8, 8), 256, GSMEM>>>(
            BB, 4*EE, EE, hh, hl, EE, whhh, whhl, EE,
            G, 4*EE, (const float*)nullptr,
            xw + (long long)t*4*EE, (long long)LL*4*EE, 0,
            (__nv_bfloat16*)nullptr, (__nv_bfloat16*)nullptr, 0, (float*)nullptr, 0);
        lstm_gates<<<(BB*EE + 255)/256, 256>>>(G, hh, hl, cbuf, hid, t);
    }

    // iteration 0 fc1: emb_concat = x[:,0:2,:] flattened (lda = L*E, K = 512)
    tgemm<<<dim3(2, 8), 256, GSMEM>>>(
        BB, EE, 2*EE, xh, xl, LL*EE, fc1wh, fc1wl, 2*EE,
        (float*)nullptr, 0, fc1_b, (const float*)nullptr, 0, 1,
        fc1h, fc1l, EE, (float*)nullptr, 0);
    tgemm<<<dim3(79, 8), 256, GSMEM>>>(
        BB, RP1, EE, fc1h, fc1l, EE, fc2wh, fc2wl, EE,
        prob, RP1, fc2_b, (const float*)nullptr, 0, 0,
        (__nv_bfloat16*)nullptr, (__nv_bfloat16*)nullptr, 0, (float*)nullptr, 0);
    softmax_kernel<<<BB, 256>>>(prob, psfh, psfl, plast);

    // iterations 1..6
    for (int i = 1; i < LL - 1; i++){
        svec_kernel<<<1, EE>>>(fc1_w, fc1_b, emb_w, i, svec);

        // emb_1 partials: psf[:, :R] @ emb_w (split-K over K=RS)
        tgemm<<<dim3(2, 8, NSPLIT), 256, GSMEM>>>(
            BB, EE, RS, psfh, psfl, RS, embTh, embTl, RS,
            (float*)nullptr, 0, (const float*)nullptr, (const float*)nullptr, 0, 0,
            (__nv_bfloat16*)nullptr, (__nv_bfloat16*)nullptr, 0, part, KCH);
        reduce_splitk<<<(BB*EE + 255)/256, 256>>>(
            part, emb1, e1h, e1l, hid + (long long)i*EE, plast);

        // fc1: relu(emb_1 @ W1a^T + svec), K = 256 over first half of fc1_w rows
        tgemm<<<dim3(2, 8), 256, GSMEM>>>(
            BB, EE, EE, e1h, e1l, EE, fc1wh, fc1wl, 2*EE,
            (float*)nullptr, 0, svec, (const float*)nullptr, 0, 1,
            fc1h, fc1l, EE, (float*)nullptr, 0);

        // fc2 -> prob (straight into d_out)
        tgemm<<<dim3(79, 8), 256, GSMEM>>>(
            BB, RP1, EE, fc1h, fc1l, EE, fc2wh, fc2wl, EE,
            prob, RP1, fc2_b, (const float*)nullptr, 0, 0,
            (__nv_bfloat16*)nullptr, (__nv_bfloat16*)nullptr, 0, (float*)nullptr, 0);

        if (i < LL - 2) softmax_kernel<<<BB, 256>>>(prob, psfh, psfl, plast);
    }

    if (out_size >= BB * RP1 + BB * 2 * EE)
        concat_kernel<<<(BB*2*EE + 255)/256, 256>>>(emb1, emb_w, outcat);
}

// round 5
// speedup vs baseline: 2.8333x; 1.1437x over previous
#include <cuda_runtime.h>
#include <cuda_bf16.h>
#include <math.h>
#include <stdint.h>

// Problem constants
#define BB 1024
#define LL 8
#define EE 256
#define RR 10000
#define RP1 10001
#define RS 10016            // padded K stride for psf/embT (mult of 32)
#define NSPLIT 8
#define KCH 1280            // split-K chunk (mult of 32)

// ------------------------- scratch (static device memory) ---------------------
__device__ float g_c[BB*EE];
__device__ float g_G[BB*4*EE];
__device__ float g_hid[BB*LL*EE];
__device__ float g_emb1[BB*EE];
__device__ float g_part[NSPLIT*BB*EE];
__device__ float g_svecs[6*EE];
__device__ float g_bsum[4*EE];
__device__ float g_plast[BB];

__device__ __nv_bfloat16 g_xh[BB*LL*EE],  g_xl[BB*LL*EE];
__device__ __nv_bfloat16 g_hh[BB*EE],     g_hl[BB*EE];
__device__ __nv_bfloat16 g_wfh[4*EE*2*EE],g_wfl[4*EE*2*EE];   // [w_hh | w_ih] fused
__device__ __nv_bfloat16 g_fc1wh[EE*2*EE],g_fc1wl[EE*2*EE];
__device__ __nv_bfloat16 g_fc2wh[(long long)RP1*EE], g_fc2wl[(long long)RP1*EE];
__device__ __nv_bfloat16 g_embTh[(long long)EE*RS],  g_embTl[(long long)EE*RS];
__device__ __nv_bfloat16 g_psfh[(long long)BB*RS],   g_psfl[(long long)BB*RS];
__device__ __nv_bfloat16 g_fc1h[BB*EE],   g_fc1l[BB*EE];
__device__ __nv_bfloat16 g_e1h[BB*EE],    g_e1l[BB*EE];

// ------------------------- PTX helpers ----------------------------------------
__device__ __forceinline__ uint32_t u32s(const void* p){
    uint32_t a;
    asm("{ .reg .u64 t; cvta.to.shared.u64 t, %1; cvt.u32.u64 %0, t; }" : "=r"(a) : "l"(p));
    return a;
}
__device__ __forceinline__ void cpa16(uint32_t dst, const void* src, uint32_t sz){
    asm volatile("cp.async.cg.shared.global [%0], [%1], 16, %2;" :: "r"(dst), "l"(src), "r"(sz));
}
__device__ __forceinline__ void cpa_commit(){ asm volatile("cp.async.commit_group;" ::: "memory"); }
__device__ __forceinline__ void ldm4(uint32_t* r, uint32_t addr){
    asm volatile("ldmatrix.sync.aligned.m8n8.x4.shared.b16 {%0,%1,%2,%3}, [%4];"
        : "=r"(r[0]), "=r"(r[1]), "=r"(r[2]), "=r"(r[3]) : "r"(addr));
}
__device__ __forceinline__ void mma_bf16(float* c, const uint32_t* a, const uint32_t* b){
    asm volatile(
        "mma.sync.aligned.m16n8k16.row.col.f32.bf16.bf16.f32 "
        "{%0,%1,%2,%3}, {%4,%5,%6,%7}, {%8,%9}, {%0,%1,%2,%3};"
        : "+f"(c[0]), "+f"(c[1]), "+f"(c[2]), "+f"(c[3])
        : "r"(a[0]), "r"(a[1]), "r"(a[2]), "r"(a[3]), "r"(b[0]), "r"(b[1]));
}
__device__ __forceinline__ void split2(float v, __nv_bfloat16& hi, __nv_bfloat16& lo){
    hi = __float2bfloat16(v);
    lo = __float2bfloat16(v - __bfloat162float(hi));
}

// ------------------------- bf16x3 NT GEMM --------------------------------------
// C[m,n] = sum_k A[m,k]*B[n,k], operands pre-split hi/lo bf16.
// BM=BN=128, BK=32, 512 threads (16 warps, 4x4 grid, 32x32 warp tiles),
// 3-stage cp.async pipeline (120 KB SMEM), rows padded to 80B.
// Dual-A: columns k >= kSplit read from (Ah2,Al2,lda2) -- used for LSTM [h|x_t].
#define ST 3
#define TILEB 10240
#define STAGEB (4*TILEB)
#define GSMEM (ST*STAGEB)

__global__ void __launch_bounds__(512,1) tgemm(
    int M, int N, int K,
    const __nv_bfloat16* __restrict__ Ah, const __nv_bfloat16* __restrict__ Al, int lda,
    const __nv_bfloat16* __restrict__ Ah2, const __nv_bfloat16* __restrict__ Al2,
    int lda2, int kSplit,
    const __nv_bfloat16* __restrict__ Bh, const __nv_bfloat16* __restrict__ Bl, int ldb,
    float* __restrict__ C, int ldc,
    const float* __restrict__ bias,
    const float* __restrict__ add, long long addStride,
    int doRelu,
    __nv_bfloat16* __restrict__ Oh, __nv_bfloat16* __restrict__ Ol, int ldo,
    float* __restrict__ part, int kChunk)
{
    extern __shared__ char smem[];
    const int tid = threadIdx.x, lane = tid & 31, wid = tid >> 5;
    const int wm = wid >> 2, wn = wid & 3;      // 4 (m) x 4 (n) warps
    const int m0 = blockIdx.y * 128, n0 = blockIdx.x * 128;

    int k0 = 0, k1 = K;
    if (part){ k0 = blockIdx.z * kChunk; k1 = min(K, k0 + kChunk); }
    const int nch = (k1 - k0) >> 5;             // K multiple of 32 everywhere

    const uint32_t sb = u32s(smem);

    // loader: 512 threads cover 128 rows x 4 16B-chunks exactly once per tile
    const int lrow = tid >> 2, lch = tid & 3;
    auto load = [&](int c){
        if (c < nch){
            uint32_t st = sb + (uint32_t)(c % ST) * STAGEB;
            int off = k0 + c * 32 + lch * 8;
            uint32_t d = st + (uint32_t)lrow * 80 + (uint32_t)lch * 16;
            {   // A hi/lo (dual-pointer on kSplit)
                int gm = m0 + lrow;
                uint32_t sz = (gm < M) ? 16u : 0u;
                int gmc = (gm < M) ? gm : 0;
                const __nv_bfloat16 *ph, *pl; long long o;
                if (off < kSplit){ o = (long long)gmc * lda  + off;          ph = Ah;  pl = Al; }
                else             { o = (long long)gmc * lda2 + (off-kSplit); ph = Ah2; pl = Al2; }
                cpa16(d,         ph + o, sz);
                cpa16(d + TILEB, pl + o, sz);
            }
            {   // B hi/lo
                int gn = n0 + lrow;
                uint32_t sz = (gn < N) ? 16u : 0u;
                long long o = (long long)((gn < N) ? gn : 0) * ldb + off;
                cpa16(d + 2*TILEB, Bh + o, sz);
                cpa16(d + 3*TILEB, Bl + o, sz);
            }
        }
        cpa_commit();
    };

    // fragment smem offsets (bytes)
    const int aq = lane >> 3, ar = lane & 7;
    const uint32_t aoff = (uint32_t)((wm*32 + (aq&1)*8 + ar) * 80 + (aq>>1) * 16);
    const uint32_t boff = (uint32_t)((wn*32 + ((lane>>4)&1)*8 + ar) * 80 + ((lane>>3)&1) * 16);

    float acc[2][4][4];
    #pragma unroll
    for (int i = 0; i < 2; i++)
        #pragma unroll
        for (int j = 0; j < 4; j++)
            #pragma unroll
            for (int q = 0; q < 4; q++) acc[i][j][q] = 0.f;

    for (int c = 0; c < ST-1; c++) load(c);

    for (int c = 0; c < nch; c++){
        asm volatile("cp.async.wait_group %0;" :: "n"(ST-2) : "memory");
        __syncthreads();
        load(c + ST - 1);

        uint32_t st = sb + (uint32_t)(c % ST) * STAGEB;
        #pragma unroll
        for (int ks = 0; ks < 2; ks++){
            uint32_t Ahr[2][4], Alr[2][4], Bhr[4][2], Blr[4][2];
            #pragma unroll
            for (int i = 0; i < 2; i++){
                ldm4(Ahr[i], st + aoff + i*1280 + ks*32);
                ldm4(Alr[i], st + TILEB + aoff + i*1280 + ks*32);
            }
            #pragma unroll
            for (int p = 0; p < 2; p++){
                uint32_t t[4];
                ldm4(t, st + 2*TILEB + boff + p*1280 + ks*32);
                Bhr[2*p][0]=t[0]; Bhr[2*p][1]=t[1]; Bhr[2*p+1][0]=t[2]; Bhr[2*p+1][1]=t[3];
                ldm4(t, st + 3*TILEB + boff + p*1280 + ks*32);
                Blr[2*p][0]=t[0]; Blr[2*p][1]=t[1]; Blr[2*p+1][0]=t[2]; Blr[2*p+1][1]=t[3];
            }
            #pragma unroll
            for (int i = 0; i < 2; i++)
                #pragma unroll
                for (int j = 0; j < 4; j++){
                    mma_bf16(acc[i][j], Ahr[i], Bhr[j]);
                    mma_bf16(acc[i][j], Ahr[i], Blr[j]);
                    mma_bf16(acc[i][j], Alr[i], Bhr[j]);
                }
        }
        __syncthreads();
    }

    // epilogue
    const int mr  = m0 + wm*32 + (lane >> 2);
    const int nc0 = n0 + wn*32 + (lane & 3)*2;

    if (part){
        float* P = part + (long long)blockIdx.z * M * N;
        #pragma unroll
        for (int i = 0; i < 2; i++)
            #pragma unroll
            for (int j = 0; j < 4; j++)
                #pragma unroll
                for (int h = 0; h < 2; h++){
                    int m = mr + i*16 + h*8, n = nc0 + j*8;
                    P[(long long)m*N + n]     = acc[i][j][2*h];
                    P[(long long)m*N + n + 1] = acc[i][j][2*h+1];
                }
        return;
    }

    #pragma unroll
    for (int i = 0; i < 2; i++)
        #pragma unroll
        for (int j = 0; j < 4; j++)
            #pragma unroll
            for (int h = 0; h < 2; h++){
                int m = mr + i*16 + h*8;
                #pragma unroll
                for (int e = 0; e < 2; e++){
                    int n = nc0 + j*8 + e;
                    if (n >= N) continue;
                    float v = acc[i][j][2*h + e];
                    if (bias) v += bias[n];
                    if (add)  v += add[(long long)m*addStride + n];
                    if (doRelu) v = fmaxf(v, 0.f);
                    if (C) C[(long long)m*ldc + n] = v;
                    if (Oh){
                        __nv_bfloat16 hi, lo; split2(v, hi, lo);
                        Oh[(long long)m*ldo + n] = hi;
                        Ol[(long long)m*ldo + n] = lo;
                    }
                }
            }
}

// ------------------------- split-K reduce + emb1 epilogue ----------------------
__global__ void reduce_splitk(const float* __restrict__ part, float* __restrict__ emb1,
                              __nv_bfloat16* __restrict__ eh, __nv_bfloat16* __restrict__ el,
                              const float* __restrict__ hidI, const float* __restrict__ plast)
{
    int idx = blockIdx.x * blockDim.x + threadIdx.x;
    if (idx >= BB * EE) return;
    int m = idx >> 8, n = idx & 255;
    float v = 0.f;
    #pragma unroll
    for (int s = 0; s < NSPLIT; s++) v += part[(long long)s * BB * EE + idx];
    v += plast[m] * hidI[(long long)m * LL * EE + n];
    emb1[idx] = v;
    __nv_bfloat16 hi, lo; split2(v, hi, lo);
    eh[idx] = hi; el[idx] = lo;
}

// ------------------------- helper kernels --------------------------------------
__global__ void conv_kernel(const float* __restrict__ src, __nv_bfloat16* __restrict__ hi,
                            __nv_bfloat16* __restrict__ lo, int n)
{
    int i = blockIdx.x * blockDim.x + threadIdx.x;
    if (i < n){ __nv_bfloat16 h, l; split2(src[i], h, l); hi[i] = h; lo[i] = l; }
}

// fused LSTM weight: row n cols [0,256) = w_hh[n], cols [256,512) = w_ih[n]
__global__ void fusew_kernel(const float* __restrict__ w_ih, const float* __restrict__ w_hh,
                             __nv_bfloat16* __restrict__ hi, __nv_bfloat16* __restrict__ lo)
{
    int i = blockIdx.x * blockDim.x + threadIdx.x;
    if (i >= 4*EE*2*EE) return;
    int n = i >> 9, k = i & 511;
    float v = (k < EE) ? w_hh[(long long)n*EE + k] : w_ih[(long long)n*EE + (k-EE)];
    __nv_bfloat16 h, l; split2(v, h, l);
    hi[i] = h; lo[i] = l;
}

__global__ void transpose_kernel(const float* __restrict__ src,
                                 __nv_bfloat16* __restrict__ dh, __nv_bfloat16* __restrict__ dl)
{
    __shared__ float tile[32][33];
    int r0 = blockIdx.x * 32, e0 = blockIdx.y * 32;
    for (int i = threadIdx.y; i < 32; i += 8){
        int r = r0 + i, e = e0 + threadIdx.x;
        tile[i][threadIdx.x] = (r < RR) ? src[(long long)r * EE + e] : 0.f;
    }
    __syncthreads();
    for (int i = threadIdx.y; i < 32; i += 8){
        int e = e0 + i, r = r0 + threadIdx.x;
        __nv_bfloat16 h, l; split2(tile[threadIdx.x][i], h, l);
        dh[(long long)e * RS + r] = h;
        dl[(long long)e * RS + r] = l;
    }
}

__global__ void gather_kernel(const int* __restrict__ bodys, const float* __restrict__ emb_w,
                              __nv_bfloat16* __restrict__ xh, __nv_bfloat16* __restrict__ xl)
{
    int bl = blockIdx.x;
    int r = bodys[bl];
    for (int i = threadIdx.x; i < EE; i += blockDim.x){
        __nv_bfloat16 h, l; split2(emb_w[(long long)r * EE + i], h, l);
        xh[(long long)bl * EE + i] = h;
        xl[(long long)bl * EE + i] = l;
    }
}

__global__ void bsum_kernel(const float* __restrict__ b_ih, const float* __restrict__ b_hh,
                            float* __restrict__ bsum)
{
    int i = threadIdx.x;
    if (i < 4 * EE) bsum[i] = b_ih[i] + b_hh[i];
}

__global__ void zinit_kernel(__nv_bfloat16* __restrict__ hh, __nv_bfloat16* __restrict__ hl,
                             float* __restrict__ c)
{
    int i = blockIdx.x * blockDim.x + threadIdx.x;
    if (i < BB * EE){ hh[i] = __float2bfloat16(0.f); hl[i] = __float2bfloat16(0.f); c[i] = 0.f; }
}

__global__ void lstm_gates(const float* __restrict__ G, __nv_bfloat16* __restrict__ hh,
                           __nv_bfloat16* __restrict__ hl, float* __restrict__ c,
                           float* __restrict__ hid, int t)
{
    int idx = blockIdx.x * blockDim.x + threadIdx.x;
    if (idx >= BB * EE) return;
    int b = idx >> 8, e = idx & 255;
    const float* g = G + (long long)b * (4 * EE);
    float gi = g[e], gf = g[EE + e], gg = g[2*EE + e], go = g[3*EE + e];
    float si = 1.f / (1.f + __expf(-gi));
    float sf = 1.f / (1.f + __expf(-gf));
    float so = 1.f / (1.f + __expf(-go));
    float cn = sf * c[idx] + si * tanhf(gg);
    c[idx] = cn;
    float hn = so * tanhf(cn);
    __nv_bfloat16 hi, lo; split2(hn, hi, lo);
    hh[idx] = hi; hl[idx] = lo;
    hid[((long long)b * LL + t) * EE + e] = hn;
}

// softmax: prob (stride RP1) -> psf hi/lo (stride RS, cols >= RR zeroed), plast[b]
__global__ void __launch_bounds__(256) softmax_kernel(
    const float* __restrict__ prob, __nv_bfloat16* __restrict__ ph,
    __nv_bfloat16* __restrict__ pl, float* __restrict__ plast)
{
    int b = blockIdx.x, tid = threadIdx.x;
    const float* x = prob + (long long)b * RP1;
    __shared__ float red[8];

    float v[40]; int cnt = 0;
    float mx = -1e30f;
    for (int i = tid; i < RP1; i += 256){ float t = x[i]; v[cnt++] = t; mx = fmaxf(mx, t); }
    for (int o = 16; o; o >>= 1) mx = fmaxf(mx, __shfl_xor_sync(0xffffffffu, mx, o));
    if ((tid & 31) == 0) red[tid >> 5] = mx;
    __syncthreads();
    mx = red[0];
    #pragma unroll
    for (int w = 1; w < 8; w++) mx = fmaxf(mx, red[w]);

    float s = 0.f;
    for (int j = 0; j < cnt; j++){ v[j] = __expf(v[j] - mx); s += v[j]; }
    for (int o = 16; o; o >>= 1) s += __shfl_xor_sync(0xffffffffu, s, o);
    __syncthreads();
    if ((tid & 31) == 0) red[tid >> 5] = s;
    __syncthreads();
    s = 0.f;
    #pragma unroll
    for (int w = 0; w < 8; w++) s += red[w];
    float inv = 1.f / s;

    __nv_bfloat16* yh = ph + (long long)b * RS;
    __nv_bfloat16* yl = pl + (long long)b * RS;
    int j = 0;
    for (int i = tid; i < RS; i += 256){
        float t = 0.f;
        if (i < RP1){ t = v[j++] * inv; }
        if (i < RR){
            __nv_bfloat16 hi, lo; split2(t, hi, lo);
            yh[i] = hi; yl[i] = lo;
        } else {
            if (i == RR) plast[b] = t;
            yh[i] = __float2bfloat16(0.f);
            yl[i] = __float2bfloat16(0.f);
        }
    }
}

// all svec vectors for iters 1..6: svecs[i-1][e] = fc1_b[e] + dot(fc1_w[e,256:512], emb_w[i+1])
__global__ void svec_all_kernel(const float* __restrict__ fc1_w, const float* __restrict__ fc1_b,
                                const float* __restrict__ emb_w, float* __restrict__ svecs)
{
    __shared__ float er[EE];
    int it = blockIdx.x;               // 0..5 -> iter = it+1, emb row = it+2
    int e = threadIdx.x;
    er[e] = emb_w[(long long)(it + 2) * EE + e];
    __syncthreads();
    const float* w = fc1_w + (long long)e * (2 * EE) + EE;
    float s = fc1_b[e];
    #pragma unroll 8
    for (int k = 0; k < EE; k++) s += w[k] * er[k];
    svecs[(long long)it * EE + e] = s;
}

__global__ void concat_kernel(const float* __restrict__ emb1,
                              const float* __restrict__ emb_w, float* __restrict__ out)
{
    int idx = blockIdx.x * blockDim.x + threadIdx.x;
    if (idx >= BB * 2 * EE) return;
    int b = idx >> 9, e = idx & 511;
    out[idx] = (e < EE) ? emb1[(long long)b * EE + e]
                        : emb_w[(long long)(LL - 1) * EE + (e - EE)];
}

// ------------------------- host launch sequence --------------------------------
template<class T> static T* sym_addr(const void* s){ void* p = nullptr; cudaGetSymbolAddress(&p, s); return (T*)p; }

extern "C" void kernel_launch(void* const* d_in, const int* in_sizes, int n_in,
                              void* d_out, int out_size)
{
    const int*   bodys = (const int*)d_in[0];
    const float* emb_w = (const float*)d_in[1];
    const float* w_ih  = (const float*)d_in[2];
    const float* w_hh  = (const float*)d_in[3];
    const float* b_ih  = (const float*)d_in[4];
    const float* b_hh  = (const float*)d_in[5];
    const float* fc1_w = (const float*)d_in[6];
    const float* fc1_b = (const float*)d_in[7];
    const float* fc2_w = (const float*)d_in[8];
    const float* fc2_b = (const float*)d_in[9];

    float* prob   = (float*)d_out;
    float* outcat = prob + (long long)BB * RP1;

    float* cbuf  = sym_addr<float>(g_c);
    float* G     = sym_addr<float>(g_G);
    float* hid   = sym_addr<float>(g_hid);
    float* emb1  = sym_addr<float>(g_emb1);
    float* part  = sym_addr<float>(g_part);
    float* svecs = sym_addr<float>(g_svecs);
    float* bsum  = sym_addr<float>(g_bsum);
    float* plast = sym_addr<float>(g_plast);

    __nv_bfloat16* xh    = sym_addr<__nv_bfloat16>(g_xh);
    __nv_bfloat16* xl    = sym_addr<__nv_bfloat16>(g_xl);
    __nv_bfloat16* hh    = sym_addr<__nv_bfloat16>(g_hh);
    __nv_bfloat16* hl    = sym_addr<__nv_bfloat16>(g_hl);
    __nv_bfloat16* wfh   = sym_addr<__nv_bfloat16>(g_wfh);
    __nv_bfloat16* wfl   = sym_addr<__nv_bfloat16>(g_wfl);
    __nv_bfloat16* fc1wh = sym_addr<__nv_bfloat16>(g_fc1wh);
    __nv_bfloat16* fc1wl = sym_addr<__nv_bfloat16>(g_fc1wl);
    __nv_bfloat16* fc2wh = sym_addr<__nv_bfloat16>(g_fc2wh);
    __nv_bfloat16* fc2wl = sym_addr<__nv_bfloat16>(g_fc2wl);
    __nv_bfloat16* embTh = sym_addr<__nv_bfloat16>(g_embTh);
    __nv_bfloat16* embTl = sym_addr<__nv_bfloat16>(g_embTl);
    __nv_bfloat16* psfh  = sym_addr<__nv_bfloat16>(g_psfh);
    __nv_bfloat16* psfl  = sym_addr<__nv_bfloat16>(g_psfl);
    __nv_bfloat16* fc1h  = sym_addr<__nv_bfloat16>(g_fc1h);
    __nv_bfloat16* fc1l  = sym_addr<__nv_bfloat16>(g_fc1l);
    __nv_bfloat16* e1h   = sym_addr<__nv_bfloat16>(g_e1h);
    __nv_bfloat16* e1l   = sym_addr<__nv_bfloat16>(g_e1l);

    const __nv_bfloat16* nbf = (const __nv_bfloat16*)nullptr;
    __nv_bfloat16* nbm = (__nv_bfloat16*)nullptr;
    const float* nf = (const float*)nullptr;

    cudaFuncSetAttribute(tgemm, cudaFuncAttributeMaxDynamicSharedMemorySize, GSMEM);

    // ---- prologue
    fusew_kernel<<<(4*EE*2*EE + 255)/256, 256>>>(w_ih, w_hh, wfh, wfl);
    conv_kernel<<<(EE*2*EE + 255)/256, 256>>>(fc1_w, fc1wh, fc1wl, EE*2*EE);
    conv_kernel<<<(RP1*EE + 255)/256, 256>>>(fc2_w, fc2wh, fc2wl, RP1*EE);
    transpose_kernel<<<dim3(RS/32, EE/32), dim3(32, 8)>>>(emb_w, embTh, embTl);
    gather_kernel<<<BB*LL, 64>>>(bodys, emb_w, xh, xl);
    bsum_kernel<<<1, 4*EE>>>(b_ih, b_hh, bsum);
    zinit_kernel<<<(BB*EE + 255)/256, 256>>>(hh, hl, cbuf);
    svec_all_kernel<<<6, EE>>>(fc1_w, fc1_b, emb_w, svecs);

    // LSTM: 8 steps; G = [h | x_t] @ [w_hh | w_ih]^T + (b_ih + b_hh)
    for (int t = 0; t < LL; t++){
        tgemm<<<dim3(8, 8), 512, GSMEM>>>(
            BB, 4*EE, 2*EE,
            hh, hl, EE,
            xh + (long long)t*EE, xl + (long long)t*EE, LL*EE, EE,
            wfh, wfl, 2*EE,
            G, 4*EE, bsum, nf, 0, 0,
            nbm, nbm, 0, (float*)nullptr, 0);
        lstm_gates<<<(BB*EE + 255)/256, 256>>>(G, hh, hl, cbuf, hid, t);
    }

    // iteration 0 fc1: emb_concat = x[:,0:2,:] contiguous per row (lda = L*E, K = 512)
    tgemm<<<dim3(2, 8), 512, GSMEM>>>(
        BB, EE, 2*EE, xh, xl, LL*EE, nbf, nbf, 0, 2*EE,
        fc1wh, fc1wl, 2*EE,
        (float*)nullptr, 0, fc1_b, nf, 0, 1,
        fc1h, fc1l, EE, (float*)nullptr, 0);
    tgemm<<<dim3(79, 8), 512, GSMEM>>>(
        BB, RP1, EE, fc1h, fc1l, EE, nbf, nbf, 0, EE,
        fc2wh, fc2wl, EE,
        prob, RP1, fc2_b, nf, 0, 0,
        nbm, nbm, 0, (float*)nullptr, 0);
    softmax_kernel<<<BB, 256>>>(prob, psfh, psfl, plast);

    // iterations 1..6
    for (int i = 1; i < LL - 1; i++){
        // emb_1 partials: psf[:, :R] @ emb_w (split-K over K=RS)
        tgemm<<<dim3(2, 8, NSPLIT), 512, GSMEM>>>(
            BB, EE, RS, psfh, psfl, RS, nbf, nbf, 0, RS,
            embTh, embTl, RS,
            (float*)nullptr, 0, nf, nf, 0, 0,
            nbm, nbm, 0, part, KCH);
        reduce_splitk<<<(BB*EE + 255)/256, 256>>>(
            part, emb1, e1h, e1l, hid + (long long)i*EE, plast);

        // fc1: relu(emb_1 @ W1a^T + svec_i)
        tgemm<<<dim3(2, 8), 512, GSMEM>>>(
            BB, EE, EE, e1h, e1l, EE, nbf, nbf, 0, EE,
            fc1wh, fc1wl, 2*EE,
            (float*)nullptr, 0, svecs + (long long)(i-1)*EE, nf, 0, 1,
            fc1h, fc1l, EE, (float*)nullptr, 0);

        // fc2 -> prob
        tgemm<<<dim3(79, 8), 512, GSMEM>>>(
            BB, RP1, EE, fc1h, fc1l, EE, nbf, nbf, 0, EE,
            fc2wh, fc2wl, EE,
            prob, RP1, fc2_b, nf, 0, 0,
            nbm, nbm, 0, (float*)nullptr, 0);

        if (i < LL - 2) softmax_kernel<<<BB, 256>>>(prob, psfh, psfl, plast);
    }

    if (out_size >= BB * RP1 + BB * 2 * EE)
        concat_kernel<<<(BB*2*EE + 255)/256, 256>>>(emb1, emb_w, outcat);
}

// round 6
// speedup vs baseline: 3.0349x; 1.0711x over previous
#include <cuda_runtime.h>
#include <cuda_bf16.h>
#include <math.h>
#include <stdint.h>

// Problem constants
#define BB 1024
#define LL 8
#define EE 256
#define RR 10000
#define RP1 10001
#define RS 10016            // padded K stride for psf/embT (mult of 32)
#define NSPLIT 8
#define KCH 1280            // split-K chunk (mult of 32)

// ------------------------- scratch (static device memory) ---------------------
__device__ float g_c[BB*EE];
__device__ float g_G[BB*4*EE];
__device__ float g_hid[BB*LL*EE];
__device__ float g_emb1[BB*EE];
__device__ float g_part[NSPLIT*BB*EE];
__device__ float g_svecs[6*EE];
__device__ float g_bsum[4*EE];
__device__ float g_plast[BB];

__device__ __nv_bfloat16 g_xh[BB*LL*EE],  g_xl[BB*LL*EE];
__device__ __nv_bfloat16 g_hh[BB*EE],     g_hl[BB*EE];
__device__ __nv_bfloat16 g_wfh[4*EE*2*EE],g_wfl[4*EE*2*EE];   // [w_hh | w_ih] fused
__device__ __nv_bfloat16 g_fc1wh[EE*2*EE],g_fc1wl[EE*2*EE];
__device__ __nv_bfloat16 g_fc2wh[(long long)RP1*EE], g_fc2wl[(long long)RP1*EE];
__device__ __nv_bfloat16 g_embTh[(long long)EE*RS],  g_embTl[(long long)EE*RS];
__device__ __nv_bfloat16 g_psfh[(long long)BB*RS],   g_psfl[(long long)BB*RS];
__device__ __nv_bfloat16 g_fc1h[BB*EE],   g_fc1l[BB*EE];
__device__ __nv_bfloat16 g_e1h[BB*EE],    g_e1l[BB*EE];

// ------------------------- PTX helpers ----------------------------------------
__device__ __forceinline__ uint32_t u32s(const void* p){
    uint32_t a;
    asm("{ .reg .u64 t; cvta.to.shared.u64 t, %1; cvt.u32.u64 %0, t; }" : "=r"(a) : "l"(p));
    return a;
}
__device__ __forceinline__ void cpa16(uint32_t dst, const void* src, uint32_t sz){
    asm volatile("cp.async.cg.shared.global [%0], [%1], 16, %2;" :: "r"(dst), "l"(src), "r"(sz));
}
__device__ __forceinline__ void cpa_commit(){ asm volatile("cp.async.commit_group;" ::: "memory"); }
__device__ __forceinline__ void ldm4(uint32_t* r, uint32_t addr){
    asm volatile("ldmatrix.sync.aligned.m8n8.x4.shared.b16 {%0,%1,%2,%3}, [%4];"
        : "=r"(r[0]), "=r"(r[1]), "=r"(r[2]), "=r"(r[3]) : "r"(addr));
}
__device__ __forceinline__ void mma_bf16(float* c, const uint32_t* a, const uint32_t* b){
    asm volatile(
        "mma.sync.aligned.m16n8k16.row.col.f32.bf16.bf16.f32 "
        "{%0,%1,%2,%3}, {%4,%5,%6,%7}, {%8,%9}, {%0,%1,%2,%3};"
        : "+f"(c[0]), "+f"(c[1]), "+f"(c[2]), "+f"(c[3])
        : "r"(a[0]), "r"(a[1]), "r"(a[2]), "r"(a[3]), "r"(b[0]), "r"(b[1]));
}
__device__ __forceinline__ void split2(float v, __nv_bfloat16& hi, __nv_bfloat16& lo){
    hi = __float2bfloat16(v);
    lo = __float2bfloat16(v - __bfloat162float(hi));
}

// ------------------------- bf16x3 NT GEMM --------------------------------------
// C[m,n] = sum_k A[m,k]*B[n,k], operands pre-split hi/lo bf16.
// BM=BN=128, BK=32, 512 threads (16 warps, 4x4 grid, 32x32 warp tiles),
// 3-stage cp.async pipeline (120 KB SMEM), rows padded to 80B.
// Dual-A: columns k >= kSplit read from (Ah2,Al2,lda2) -- used for LSTM [h|x_t].
#define ST 3
#define TILEB 10240
#define STAGEB (4*TILEB)
#define GSMEM (ST*STAGEB)

__global__ void __launch_bounds__(512,1) tgemm(
    int M, int N, int K,
    const __nv_bfloat16* __restrict__ Ah, const __nv_bfloat16* __restrict__ Al, int lda,
    const __nv_bfloat16* __restrict__ Ah2, const __nv_bfloat16* __restrict__ Al2,
    int lda2, int kSplit,
    const __nv_bfloat16* __restrict__ Bh, const __nv_bfloat16* __restrict__ Bl, int ldb,
    float* __restrict__ C, int ldc,
    const float* __restrict__ bias,
    const float* __restrict__ add, long long addStride,
    int doRelu,
    __nv_bfloat16* __restrict__ Oh, __nv_bfloat16* __restrict__ Ol, int ldo,
    float* __restrict__ part, int kChunk)
{
    extern __shared__ char smem[];
    const int tid = threadIdx.x, lane = tid & 31, wid = tid >> 5;
    const int wm = wid >> 2, wn = wid & 3;      // 4 (m) x 4 (n) warps
    const int m0 = blockIdx.y * 128, n0 = blockIdx.x * 128;

    int k0 = 0, k1 = K;
    if (part){ k0 = blockIdx.z * kChunk; k1 = min(K, k0 + kChunk); }
    const int nch = (k1 - k0) >> 5;             // K multiple of 32 everywhere

    const uint32_t sb = u32s(smem);

    // loader: 512 threads cover 128 rows x 4 16B-chunks exactly once per tile
    const int lrow = tid >> 2, lch = tid & 3;
    auto load = [&](int c){
        if (c < nch){
            uint32_t st = sb + (uint32_t)(c % ST) * STAGEB;
            int off = k0 + c * 32 + lch * 8;
            uint32_t d = st + (uint32_t)lrow * 80 + (uint32_t)lch * 16;
            {   // A hi/lo (dual-pointer on kSplit)
                int gm = m0 + lrow;
                uint32_t sz = (gm < M) ? 16u : 0u;
                int gmc = (gm < M) ? gm : 0;
                const __nv_bfloat16 *ph, *pl; long long o;
                if (off < kSplit){ o = (long long)gmc * lda  + off;          ph = Ah;  pl = Al; }
                else             { o = (long long)gmc * lda2 + (off-kSplit); ph = Ah2; pl = Al2; }
                cpa16(d,         ph + o, sz);
                cpa16(d + TILEB, pl + o, sz);
            }
            {   // B hi/lo
                int gn = n0 + lrow;
                uint32_t sz = (gn < N) ? 16u : 0u;
                long long o = (long long)((gn < N) ? gn : 0) * ldb + off;
                cpa16(d + 2*TILEB, Bh + o, sz);
                cpa16(d + 3*TILEB, Bl + o, sz);
            }
        }
        cpa_commit();
    };

    // fragment smem offsets (bytes)
    const int aq = lane >> 3, ar = lane & 7;
    const uint32_t aoff = (uint32_t)((wm*32 + (aq&1)*8 + ar) * 80 + (aq>>1) * 16);
    const uint32_t boff = (uint32_t)((wn*32 + ((lane>>4)&1)*8 + ar) * 80 + ((lane>>3)&1) * 16);

    float acc[2][4][4];
    #pragma unroll
    for (int i = 0; i < 2; i++)
        #pragma unroll
        for (int j = 0; j < 4; j++)
            #pragma unroll
            for (int q = 0; q < 4; q++) acc[i][j][q] = 0.f;

    for (int c = 0; c < ST-1; c++) load(c);

    for (int c = 0; c < nch; c++){
        asm volatile("cp.async.wait_group %0;" :: "n"(ST-2) : "memory");
        __syncthreads();
        load(c + ST - 1);

        uint32_t st = sb + (uint32_t)(c % ST) * STAGEB;
        #pragma unroll
        for (int ks = 0; ks < 2; ks++){
            uint32_t Ahr[2][4], Alr[2][4], Bhr[4][2], Blr[4][2];
            #pragma unroll
            for (int i = 0; i < 2; i++){
                ldm4(Ahr[i], st + aoff + i*1280 + ks*32);
                ldm4(Alr[i], st + TILEB + aoff + i*1280 + ks*32);
            }
            #pragma unroll
            for (int p = 0; p < 2; p++){
                uint32_t t[4];
                ldm4(t, st + 2*TILEB + boff + p*1280 + ks*32);
                Bhr[2*p][0]=t[0]; Bhr[2*p][1]=t[1]; Bhr[2*p+1][0]=t[2]; Bhr[2*p+1][1]=t[3];
                ldm4(t, st + 3*TILEB + boff + p*1280 + ks*32);
                Blr[2*p][0]=t[0]; Blr[2*p][1]=t[1]; Blr[2*p+1][0]=t[2]; Blr[2*p+1][1]=t[3];
            }
            #pragma unroll
            for (int i = 0; i < 2; i++)
                #pragma unroll
                for (int j = 0; j < 4; j++){
                    mma_bf16(acc[i][j], Ahr[i], Bhr[j]);
                    mma_bf16(acc[i][j], Ahr[i], Blr[j]);
                    mma_bf16(acc[i][j], Alr[i], Bhr[j]);
                }
        }
        __syncthreads();
    }

    // epilogue
    const int mr  = m0 + wm*32 + (lane >> 2);
    const int nc0 = n0 + wn*32 + (lane & 3)*2;

    if (part){
        float* P = part + (long long)blockIdx.z * M * N;
        #pragma unroll
        for (int i = 0; i < 2; i++)
            #pragma unroll
            for (int j = 0; j < 4; j++)
                #pragma unroll
                for (int h = 0; h < 2; h++){
                    int m = mr + i*16 + h*8, n = nc0 + j*8;
                    P[(long long)m*N + n]     = acc[i][j][2*h];
                    P[(long long)m*N + n + 1] = acc[i][j][2*h+1];
                }
        return;
    }

    #pragma unroll
    for (int i = 0; i < 2; i++)
        #pragma unroll
        for (int j = 0; j < 4; j++)
            #pragma unroll
            for (int h = 0; h < 2; h++){
                int m = mr + i*16 + h*8;
                #pragma unroll
                for (int e = 0; e < 2; e++){
                    int n = nc0 + j*8 + e;
                    if (n >= N) continue;
                    float v = acc[i][j][2*h + e];
                    if (bias) v += bias[n];
                    if (add)  v += add[(long long)m*addStride + n];
                    if (doRelu) v = fmaxf(v, 0.f);
                    if (C) C[(long long)m*ldc + n] = v;
                    if (Oh){
                        __nv_bfloat16 hi, lo; split2(v, hi, lo);
                        Oh[(long long)m*ldo + n] = hi;
                        Ol[(long long)m*ldo + n] = lo;
                    }
                }
            }
}

// ------------------------- split-K reduce + emb1 epilogue ----------------------
__global__ void reduce_splitk(const float* __restrict__ part, float* __restrict__ emb1,
                              __nv_bfloat16* __restrict__ eh, __nv_bfloat16* __restrict__ el,
                              const float* __restrict__ hidI, const float* __restrict__ plast)
{
    int idx = blockIdx.x * blockDim.x + threadIdx.x;
    if (idx >= BB * EE) return;
    int m = idx >> 8, n = idx & 255;
    float v = 0.f;
    #pragma unroll
    for (int s = 0; s < NSPLIT; s++) v += part[(long long)s * BB * EE + idx];
    v += plast[m] * hidI[(long long)m * LL * EE + n];
    emb1[idx] = v;
    __nv_bfloat16 hi, lo; split2(v, hi, lo);
    eh[idx] = hi; el[idx] = lo;
}

// ------------------------- helper kernels --------------------------------------
__global__ void conv_kernel(const float* __restrict__ src, __nv_bfloat16* __restrict__ hi,
                            __nv_bfloat16* __restrict__ lo, int n)
{
    int i = blockIdx.x * blockDim.x + threadIdx.x;
    if (i < n){ __nv_bfloat16 h, l; split2(src[i], h, l); hi[i] = h; lo[i] = l; }
}

// fused LSTM weight: row n cols [0,256) = w_hh[n], cols [256,512) = w_ih[n]
__global__ void fusew_kernel(const float* __restrict__ w_ih, const float* __restrict__ w_hh,
                             __nv_bfloat16* __restrict__ hi, __nv_bfloat16* __restrict__ lo)
{
    int i = blockIdx.x * blockDim.x + threadIdx.x;
    if (i >= 4*EE*2*EE) return;
    int n = i >> 9, k = i & 511;
    float v = (k < EE) ? w_hh[(long long)n*EE + k] : w_ih[(long long)n*EE + (k-EE)];
    __nv_bfloat16 h, l; split2(v, h, l);
    hi[i] = h; lo[i] = l;
}

__global__ void transpose_kernel(const float* __restrict__ src,
                                 __nv_bfloat16* __restrict__ dh, __nv_bfloat16* __restrict__ dl)
{
    __shared__ float tile[32][33];
    int r0 = blockIdx.x * 32, e0 = blockIdx.y * 32;
    for (int i = threadIdx.y; i < 32; i += 8){
        int r = r0 + i, e = e0 + threadIdx.x;
        tile[i][threadIdx.x] = (r < RR) ? src[(long long)r * EE + e] : 0.f;
    }
    __syncthreads();
    for (int i = threadIdx.y; i < 32; i += 8){
        int e = e0 + i, r = r0 + threadIdx.x;
        __nv_bfloat16 h, l; split2(tile[threadIdx.x][i], h, l);
        dh[(long long)e * RS + r] = h;
        dl[(long long)e * RS + r] = l;
    }
}

__global__ void gather_kernel(const int* __restrict__ bodys, const float* __restrict__ emb_w,
                              __nv_bfloat16* __restrict__ xh, __nv_bfloat16* __restrict__ xl)
{
    int bl = blockIdx.x;
    int r = bodys[bl];
    for (int i = threadIdx.x; i < EE; i += blockDim.x){
        __nv_bfloat16 h, l; split2(emb_w[(long long)r * EE + i], h, l);
        xh[(long long)bl * EE + i] = h;
        xl[(long long)bl * EE + i] = l;
    }
}

__global__ void bsum_kernel(const float* __restrict__ b_ih, const float* __restrict__ b_hh,
                            float* __restrict__ bsum)
{
    int i = threadIdx.x;
    if (i < 4 * EE) bsum[i] = b_ih[i] + b_hh[i];
}

__global__ void zinit_kernel(__nv_bfloat16* __restrict__ hh, __nv_bfloat16* __restrict__ hl,
                             float* __restrict__ c)
{
    int i = blockIdx.x * blockDim.x + threadIdx.x;
    if (i < BB * EE){ hh[i] = __float2bfloat16(0.f); hl[i] = __float2bfloat16(0.f); c[i] = 0.f; }
}

__global__ void lstm_gates(const float* __restrict__ G, __nv_bfloat16* __restrict__ hh,
                           __nv_bfloat16* __restrict__ hl, float* __restrict__ c,
                           float* __restrict__ hid, int t)
{
    int idx = blockIdx.x * blockDim.x + threadIdx.x;
    if (idx >= BB * EE) return;
    int b = idx >> 8, e = idx & 255;
    const float* g = G + (long long)b * (4 * EE);
    float gi = g[e], gf = g[EE + e], gg = g[2*EE + e], go = g[3*EE + e];
    float si = 1.f / (1.f + __expf(-gi));
    float sf = 1.f / (1.f + __expf(-gf));
    float so = 1.f / (1.f + __expf(-go));
    float cn = sf * c[idx] + si * tanhf(gg);
    c[idx] = cn;
    float hn = so * tanhf(cn);
    __nv_bfloat16 hi, lo; split2(hn, hi, lo);
    hh[idx] = hi; hl[idx] = lo;
    hid[((long long)b * LL + t) * EE + e] = hn;
}

// softmax: prob (stride RP1) -> psf hi/lo (stride RS, cols >= RR zeroed), plast[b].
// NOTE: compile-time trip count (40) so v[] is statically indexed -> registers,
// no local-memory spill.
#define SMX_IT 40
__global__ void __launch_bounds__(256) softmax_kernel(
    const float* __restrict__ prob, __nv_bfloat16* __restrict__ ph,
    __nv_bfloat16* __restrict__ pl, float* __restrict__ plast)
{
    int b = blockIdx.x, tid = threadIdx.x;
    const float* x = prob + (long long)b * RP1;
    __shared__ float red[8];

    float v[SMX_IT];
    float mx = -1e30f;
    #pragma unroll
    for (int j = 0; j < SMX_IT; j++){
        int i = tid + j * 256;
        float t = (i < RP1) ? x[i] : -1e30f;
        v[j] = t; mx = fmaxf(mx, t);
    }
    #pragma unroll
    for (int o = 16; o; o >>= 1) mx = fmaxf(mx, __shfl_xor_sync(0xffffffffu, mx, o));
    if ((tid & 31) == 0) red[tid >> 5] = mx;
    __syncthreads();
    mx = red[0];
    #pragma unroll
    for (int w = 1; w < 8; w++) mx = fmaxf(mx, red[w]);

    float s = 0.f;
    #pragma unroll
    for (int j = 0; j < SMX_IT; j++){ v[j] = __expf(v[j] - mx); s += v[j]; }
    #pragma unroll
    for (int o = 16; o; o >>= 1) s += __shfl_xor_sync(0xffffffffu, s, o);
    __syncthreads();
    if ((tid & 31) == 0) red[tid >> 5] = s;
    __syncthreads();
    s = 0.f;
    #pragma unroll
    for (int w = 0; w < 8; w++) s += red[w];
    float inv = 1.f / s;

    __nv_bfloat16* yh = ph + (long long)b * RS;
    __nv_bfloat16* yl = pl + (long long)b * RS;
    const __nv_bfloat16 z = __float2bfloat16(0.f);
    #pragma unroll
    for (int j = 0; j < SMX_IT; j++){
        int i = tid + j * 256;
        if (i < RR){
            __nv_bfloat16 hi, lo; split2(v[j] * inv, hi, lo);
            yh[i] = hi; yl[i] = lo;
        } else if (i < RS){
            if (i == RR) plast[b] = v[j] * inv;
            yh[i] = z; yl[i] = z;
        }
    }
}

// all svec vectors for iters 1..6: svecs[i-1][e] = fc1_b[e] + dot(fc1_w[e,256:512], emb_w[i+1])
__global__ void svec_all_kernel(const float* __restrict__ fc1_w, const float* __restrict__ fc1_b,
                                const float* __restrict__ emb_w, float* __restrict__ svecs)
{
    __shared__ float er[EE];
    int it = blockIdx.x;               // 0..5 -> iter = it+1, emb row = it+2
    int e = threadIdx.x;
    er[e] = emb_w[(long long)(it + 2) * EE + e];
    __syncthreads();
    const float* w = fc1_w + (long long)e * (2 * EE) + EE;
    float s = fc1_b[e];
    #pragma unroll 8
    for (int k = 0; k < EE; k++) s += w[k] * er[k];
    svecs[(long long)it * EE + e] = s;
}

__global__ void concat_kernel(const float* __restrict__ emb1,
                              const float* __restrict__ emb_w, float* __restrict__ out)
{
    int idx = blockIdx.x * blockDim.x + threadIdx.x;
    if (idx >= BB * 2 * EE) return;
    int b = idx >> 9, e = idx & 511;
    out[idx] = (e < EE) ? emb1[(long long)b * EE + e]
                        : emb_w[(long long)(LL - 1) * EE + (e - EE)];
}

// ------------------------- host launch sequence --------------------------------
template<class T> static T* sym_addr(const void* s){ void* p = nullptr; cudaGetSymbolAddress(&p, s); return (T*)p; }

extern "C" void kernel_launch(void* const* d_in, const int* in_sizes, int n_in,
                              void* d_out, int out_size)
{
    const int*   bodys = (const int*)d_in[0];
    const float* emb_w = (const float*)d_in[1];
    const float* w_ih  = (const float*)d_in[2];
    const float* w_hh  = (const float*)d_in[3];
    const float* b_ih  = (const float*)d_in[4];
    const float* b_hh  = (const float*)d_in[5];
    const float* fc1_w = (const float*)d_in[6];
    const float* fc1_b = (const float*)d_in[7];
    const float* fc2_w = (const float*)d_in[8];
    const float* fc2_b = (const float*)d_in[9];

    float* prob   = (float*)d_out;
    float* outcat = prob + (long long)BB * RP1;

    float* cbuf  = sym_addr<float>(g_c);
    float* G     = sym_addr<float>(g_G);
    float* hid   = sym_addr<float>(g_hid);
    float* emb1  = sym_addr<float>(g_emb1);
    float* part  = sym_addr<float>(g_part);
    float* svecs = sym_addr<float>(g_svecs);
    float* bsum  = sym_addr<float>(g_bsum);
    float* plast = sym_addr<float>(g_plast);

    __nv_bfloat16* xh    = sym_addr<__nv_bfloat16>(g_xh);
    __nv_bfloat16* xl    = sym_addr<__nv_bfloat16>(g_xl);
    __nv_bfloat16* hh    = sym_addr<__nv_bfloat16>(g_hh);
    __nv_bfloat16* hl    = sym_addr<__nv_bfloat16>(g_hl);
    __nv_bfloat16* wfh   = sym_addr<__nv_bfloat16>(g_wfh);
    __nv_bfloat16* wfl   = sym_addr<__nv_bfloat16>(g_wfl);
    __nv_bfloat16* fc1wh = sym_addr<__nv_bfloat16>(g_fc1wh);
    __nv_bfloat16* fc1wl = sym_addr<__nv_bfloat16>(g_fc1wl);
    __nv_bfloat16* fc2wh = sym_addr<__nv_bfloat16>(g_fc2wh);
    __nv_bfloat16* fc2wl = sym_addr<__nv_bfloat16>(g_fc2wl);
    __nv_bfloat16* embTh = sym_addr<__nv_bfloat16>(g_embTh);
    __nv_bfloat16* embTl = sym_addr<__nv_bfloat16>(g_embTl);
    __nv_bfloat16* psfh  = sym_addr<__nv_bfloat16>(g_psfh);
    __nv_bfloat16* psfl  = sym_addr<__nv_bfloat16>(g_psfl);
    __nv_bfloat16* fc1h  = sym_addr<__nv_bfloat16>(g_fc1h);
    __nv_bfloat16* fc1l  = sym_addr<__nv_bfloat16>(g_fc1l);
    __nv_bfloat16* e1h   = sym_addr<__nv_bfloat16>(g_e1h);
    __nv_bfloat16* e1l   = sym_addr<__nv_bfloat16>(g_e1l);

    const __nv_bfloat16* nbf = (const __nv_bfloat16*)nullptr;
    __nv_bfloat16* nbm = (__nv_bfloat16*)nullptr;
    const float* nf = (const float*)nullptr;

    cudaFuncSetAttribute(tgemm, cudaFuncAttributeMaxDynamicSharedMemorySize, GSMEM);

    // ---- prologue
    fusew_kernel<<<(4*EE*2*EE + 255)/256, 256>>>(w_ih, w_hh, wfh, wfl);
    conv_kernel<<<(EE*2*EE + 255)/256, 256>>>(fc1_w, fc1wh, fc1wl, EE*2*EE);
    conv_kernel<<<(RP1*EE + 255)/256, 256>>>(fc2_w, fc2wh, fc2wl, RP1*EE);
    transpose_kernel<<<dim3(RS/32, EE/32), dim3(32, 8)>>>(emb_w, embTh, embTl);
    gather_kernel<<<BB*LL, 64>>>(bodys, emb_w, xh, xl);
    bsum_kernel<<<1, 4*EE>>>(b_ih, b_hh, bsum);
    zinit_kernel<<<(BB*EE + 255)/256, 256>>>(hh, hl, cbuf);
    svec_all_kernel<<<6, EE>>>(fc1_w, fc1_b, emb_w, svecs);

    // LSTM: 8 steps; G = [h | x_t] @ [w_hh | w_ih]^T + (b_ih + b_hh)
    for (int t = 0; t < LL; t++){
        tgemm<<<dim3(8, 8), 512, GSMEM>>>(
            BB, 4*EE, 2*EE,
            hh, hl, EE,
            xh + (long long)t*EE, xl + (long long)t*EE, LL*EE, EE,
            wfh, wfl, 2*EE,
            G, 4*EE, bsum, nf, 0, 0,
            nbm, nbm, 0, (float*)nullptr, 0);
        lstm_gates<<<(BB*EE + 255)/256, 256>>>(G, hh, hl, cbuf, hid, t);
    }

    // iteration 0 fc1: emb_concat = x[:,0:2,:] contiguous per row (lda = L*E, K = 512)
    tgemm<<<dim3(2, 8), 512, GSMEM>>>(
        BB, EE, 2*EE, xh, xl, LL*EE, nbf, nbf, 0, 2*EE,
        fc1wh, fc1wl, 2*EE,
        (float*)nullptr, 0, fc1_b, nf, 0, 1,
        fc1h, fc1l, EE, (float*)nullptr, 0);
    tgemm<<<dim3(79, 8), 512, GSMEM>>>(
        BB, RP1, EE, fc1h, fc1l, EE, nbf, nbf, 0, EE,
        fc2wh, fc2wl, EE,
        prob, RP1, fc2_b, nf, 0, 0,
        nbm, nbm, 0, (float*)nullptr, 0);
    softmax_kernel<<<BB, 256>>>(prob, psfh, psfl, plast);

    // iterations 1..6
    for (int i = 1; i < LL - 1; i++){
        // emb_1 partials: psf[:, :R] @ emb_w (split-K over K=RS)
        tgemm<<<dim3(2, 8, NSPLIT), 512, GSMEM>>>(
            BB, EE, RS, psfh, psfl, RS, nbf, nbf, 0, RS,
            embTh, embTl, RS,
            (float*)nullptr, 0, nf, nf, 0, 0,
            nbm, nbm, 0, part, KCH);
        reduce_splitk<<<(BB*EE + 255)/256, 256>>>(
            part, emb1, e1h, e1l, hid + (long long)i*EE, plast);

        // fc1: relu(emb_1 @ W1a^T + svec_i)
        tgemm<<<dim3(2, 8), 512, GSMEM>>>(
            BB, EE, EE, e1h, e1l, EE, nbf, nbf, 0, EE,
            fc1wh, fc1wl, 2*EE,
            (float*)nullptr, 0, svecs + (long long)(i-1)*EE, nf, 0, 1,
            fc1h, fc1l, EE, (float*)nullptr, 0);

        // fc2 -> prob
        tgemm<<<dim3(79, 8), 512, GSMEM>>>(
            BB, RP1, EE, fc1h, fc1l, EE, nbf, nbf, 0, EE,
            fc2wh, fc2wl, EE,
            prob, RP1, fc2_b, nf, 0, 0,
            nbm, nbm, 0, (float*)nullptr, 0);

        if (i < LL - 2) softmax_kernel<<<BB, 256>>>(prob, psfh, psfl, plast);
    }

    if (out_size >= BB * RP1 + BB * 2 * EE)
        concat_kernel<<<(BB*2*EE + 255)/256, 256>>>(emb1, emb_w, outcat);
}

// round 7
// speedup vs baseline: 3.3754x; 1.1122x over previous
#include <cuda_runtime.h>
#include <cuda_bf16.h>
#include <math.h>
#include <stdint.h>

// Problem constants
#define BB 1024
#define LL 8
#define EE 256
#define RR 10000
#define RP1 10001
#define RS 10016            // padded K stride for psf/embT (mult of 32)
#define NSPLIT 9
#define KCH 1120            // split-K chunk (mult of 32); 9*1120 >= 10016

// ------------------------- scratch (static device memory) ---------------------
__device__ float g_c[BB*EE];
__device__ float g_G[BB*4*EE];
__device__ float g_hid[BB*LL*EE];
__device__ float g_emb1[BB*EE];
__device__ float g_part[NSPLIT*BB*EE];
__device__ float g_svecs[6*EE];
__device__ float g_bsum[4*EE];
__device__ float g_plast[BB];

__device__ __nv_bfloat16 g_xh[BB*LL*EE],  g_xl[BB*LL*EE];
__device__ __nv_bfloat16 g_hh[BB*EE],     g_hl[BB*EE];
__device__ __nv_bfloat16 g_wfh[4*EE*2*EE],g_wfl[4*EE*2*EE];   // [w_hh | w_ih] fused
__device__ __nv_bfloat16 g_fc1wh[EE*2*EE],g_fc1wl[EE*2*EE];
__device__ __nv_bfloat16 g_fc2wh[(long long)RP1*EE], g_fc2wl[(long long)RP1*EE];
__device__ __nv_bfloat16 g_embTh[(long long)EE*RS],  g_embTl[(long long)EE*RS];
__device__ __nv_bfloat16 g_psfh[(long long)BB*RS],   g_psfl[(long long)BB*RS];
__device__ __nv_bfloat16 g_fc1h[BB*EE],   g_fc1l[BB*EE];
__device__ __nv_bfloat16 g_e1h[BB*EE],    g_e1l[BB*EE];

// ------------------------- PTX helpers ----------------------------------------
__device__ __forceinline__ uint32_t u32s(const void* p){
    uint32_t a;
    asm("{ .reg .u64 t; cvta.to.shared.u64 t, %1; cvt.u32.u64 %0, t; }" : "=r"(a) : "l"(p));
    return a;
}
__device__ __forceinline__ void cpa16(uint32_t dst, const void* src, uint32_t sz){
    asm volatile("cp.async.cg.shared.global [%0], [%1], 16, %2;" :: "r"(dst), "l"(src), "r"(sz));
}
__device__ __forceinline__ void cpa_commit(){ asm volatile("cp.async.commit_group;" ::: "memory"); }
__device__ __forceinline__ void ldm4(uint32_t* r, uint32_t addr){
    asm volatile("ldmatrix.sync.aligned.m8n8.x4.shared.b16 {%0,%1,%2,%3}, [%4];"
        : "=r"(r[0]), "=r"(r[1]), "=r"(r[2]), "=r"(r[3]) : "r"(addr));
}
__device__ __forceinline__ void mma_bf16(float* c, const uint32_t* a, const uint32_t* b){
    asm volatile(
        "mma.sync.aligned.m16n8k16.row.col.f32.bf16.bf16.f32 "
        "{%0,%1,%2,%3}, {%4,%5,%6,%7}, {%8,%9}, {%0,%1,%2,%3};"
        : "+f"(c[0]), "+f"(c[1]), "+f"(c[2]), "+f"(c[3])
        : "r"(a[0]), "r"(a[1]), "r"(a[2]), "r"(a[3]), "r"(b[0]), "r"(b[1]));
}
__device__ __forceinline__ void split2(float v, __nv_bfloat16& hi, __nv_bfloat16& lo){
    hi = __float2bfloat16(v);
    lo = __float2bfloat16(v - __bfloat162float(hi));
}

// ------------------------- bf16x3 NT GEMM --------------------------------------
// C[m,n] = sum_k A[m,k]*B[n,k], operands pre-split hi/lo bf16.
// BM=BN=128, BK=32, 512 threads (16 warps, 4x4 grid, 32x32 warp tiles),
// 3-stage cp.async pipeline (120 KB SMEM), rows padded to 80B.
// Dual-A: columns k >= kSplit read from (Ah2,Al2,lda2) -- used for LSTM [h|x_t].
#define ST 3
#define TILEB 10240
#define STAGEB (4*TILEB)
#define GSMEM (ST*STAGEB)

__global__ void __launch_bounds__(512,1) tgemm(
    int M, int N, int K,
    const __nv_bfloat16* __restrict__ Ah, const __nv_bfloat16* __restrict__ Al, int lda,
    const __nv_bfloat16* __restrict__ Ah2, const __nv_bfloat16* __restrict__ Al2,
    int lda2, int kSplit,
    const __nv_bfloat16* __restrict__ Bh, const __nv_bfloat16* __restrict__ Bl, int ldb,
    float* __restrict__ C, int ldc,
    const float* __restrict__ bias,
    const float* __restrict__ add, long long addStride,
    int doRelu,
    __nv_bfloat16* __restrict__ Oh, __nv_bfloat16* __restrict__ Ol, int ldo,
    float* __restrict__ part, int kChunk)
{
    extern __shared__ char smem[];
    const int tid = threadIdx.x, lane = tid & 31, wid = tid >> 5;
    const int wm = wid >> 2, wn = wid & 3;      // 4 (m) x 4 (n) warps
    const int m0 = blockIdx.y * 128, n0 = blockIdx.x * 128;

    int k0 = 0, k1 = K;
    if (part){ k0 = blockIdx.z * kChunk; k1 = min(K, k0 + kChunk); }
    const int nch = (k1 - k0) >> 5;             // K multiple of 32 everywhere

    const uint32_t sb = u32s(smem);

    // loader: 512 threads cover 128 rows x 4 16B-chunks exactly once per tile
    const int lrow = tid >> 2, lch = tid & 3;
    auto load = [&](int c){
        if (c < nch){
            uint32_t st = sb + (uint32_t)(c % ST) * STAGEB;
            int off = k0 + c * 32 + lch * 8;
            uint32_t d = st + (uint32_t)lrow * 80 + (uint32_t)lch * 16;
            {   // A hi/lo (dual-pointer on kSplit)
                int gm = m0 + lrow;
                uint32_t sz = (gm < M) ? 16u : 0u;
                int gmc = (gm < M) ? gm : 0;
                const __nv_bfloat16 *ph, *pl; long long o;
                if (off < kSplit){ o = (long long)gmc * lda  + off;          ph = Ah;  pl = Al; }
                else             { o = (long long)gmc * lda2 + (off-kSplit); ph = Ah2; pl = Al2; }
                cpa16(d,         ph + o, sz);
                cpa16(d + TILEB, pl + o, sz);
            }
            {   // B hi/lo
                int gn = n0 + lrow;
                uint32_t sz = (gn < N) ? 16u : 0u;
                long long o = (long long)((gn < N) ? gn : 0) * ldb + off;
                cpa16(d + 2*TILEB, Bh + o, sz);
                cpa16(d + 3*TILEB, Bl + o, sz);
            }
        }
        cpa_commit();
    };

    // fragment smem offsets (bytes)
    const int aq = lane >> 3, ar = lane & 7;
    const uint32_t aoff = (uint32_t)((wm*32 + (aq&1)*8 + ar) * 80 + (aq>>1) * 16);
    const uint32_t boff = (uint32_t)((wn*32 + ((lane>>4)&1)*8 + ar) * 80 + ((lane>>3)&1) * 16);

    float acc[2][4][4];
    #pragma unroll
    for (int i = 0; i < 2; i++)
        #pragma unroll
        for (int j = 0; j < 4; j++)
            #pragma unroll
            for (int q = 0; q < 4; q++) acc[i][j][q] = 0.f;

    for (int c = 0; c < ST-1; c++) load(c);

    for (int c = 0; c < nch; c++){
        asm volatile("cp.async.wait_group %0;" :: "n"(ST-2) : "memory");
        __syncthreads();
        load(c + ST - 1);

        uint32_t st = sb + (uint32_t)(c % ST) * STAGEB;
        #pragma unroll
        for (int ks = 0; ks < 2; ks++){
            uint32_t Ahr[2][4], Alr[2][4], Bhr[4][2], Blr[4][2];
            #pragma unroll
            for (int i = 0; i < 2; i++){
                ldm4(Ahr[i], st + aoff + i*1280 + ks*32);
                ldm4(Alr[i], st + TILEB + aoff + i*1280 + ks*32);
            }
            #pragma unroll
            for (int p = 0; p < 2; p++){
                uint32_t t[4];
                ldm4(t, st + 2*TILEB + boff + p*1280 + ks*32);
                Bhr[2*p][0]=t[0]; Bhr[2*p][1]=t[1]; Bhr[2*p+1][0]=t[2]; Bhr[2*p+1][1]=t[3];
                ldm4(t, st + 3*TILEB + boff + p*1280 + ks*32);
                Blr[2*p][0]=t[0]; Blr[2*p][1]=t[1]; Blr[2*p+1][0]=t[2]; Blr[2*p+1][1]=t[3];
            }
            #pragma unroll
            for (int i = 0; i < 2; i++)
                #pragma unroll
                for (int j = 0; j < 4; j++){
                    mma_bf16(acc[i][j], Ahr[i], Bhr[j]);
                    mma_bf16(acc[i][j], Ahr[i], Blr[j]);
                    mma_bf16(acc[i][j], Alr[i], Bhr[j]);
                }
        }
        __syncthreads();
    }

    // epilogue
    const int mr  = m0 + wm*32 + (lane >> 2);
    const int nc0 = n0 + wn*32 + (lane & 3)*2;

    if (part){
        float* P = part + (long long)blockIdx.z * M * N;
        #pragma unroll
        for (int i = 0; i < 2; i++)
            #pragma unroll
            for (int j = 0; j < 4; j++)
                #pragma unroll
                for (int h = 0; h < 2; h++){
                    int m = mr + i*16 + h*8, n = nc0 + j*8;
                    P[(long long)m*N + n]     = acc[i][j][2*h];
                    P[(long long)m*N + n + 1] = acc[i][j][2*h+1];
                }
        return;
    }

    #pragma unroll
    for (int i = 0; i < 2; i++)
        #pragma unroll
        for (int j = 0; j < 4; j++)
            #pragma unroll
            for (int h = 0; h < 2; h++){
                int m = mr + i*16 + h*8;
                #pragma unroll
                for (int e = 0; e < 2; e++){
                    int n = nc0 + j*8 + e;
                    if (n >= N) continue;
                    float v = acc[i][j][2*h + e];
                    if (bias) v += bias[n];
                    if (add)  v += add[(long long)m*addStride + n];
                    if (doRelu) v = fmaxf(v, 0.f);
                    if (C) C[(long long)m*ldc + n] = v;
                    if (Oh){
                        __nv_bfloat16 hi, lo; split2(v, hi, lo);
                        Oh[(long long)m*ldo + n] = hi;
                        Ol[(long long)m*ldo + n] = lo;
                    }
                }
            }
}

// ------------------------- split-K reduce + emb1 epilogue ----------------------
__global__ void reduce_splitk(const float* __restrict__ part, float* __restrict__ emb1,
                              __nv_bfloat16* __restrict__ eh, __nv_bfloat16* __restrict__ el,
                              const float* __restrict__ hidI, const float* __restrict__ plast)
{
    int idx = blockIdx.x * blockDim.x + threadIdx.x;
    if (idx >= BB * EE) return;
    int m = idx >> 8, n = idx & 255;
    float v = 0.f;
    #pragma unroll
    for (int s = 0; s < NSPLIT; s++) v += part[(long long)s * BB * EE + idx];
    v += plast[m] * hidI[(long long)m * LL * EE + n];
    emb1[idx] = v;
    __nv_bfloat16 hi, lo; split2(v, hi, lo);
    eh[idx] = hi; el[idx] = lo;
}

// ------------------------- helper kernels --------------------------------------
__global__ void conv_kernel(const float* __restrict__ src, __nv_bfloat16* __restrict__ hi,
                            __nv_bfloat16* __restrict__ lo, int n)
{
    int i = blockIdx.x * blockDim.x + threadIdx.x;
    if (i < n){ __nv_bfloat16 h, l; split2(src[i], h, l); hi[i] = h; lo[i] = l; }
}

// fused LSTM weight: row n cols [0,256) = w_hh[n], cols [256,512) = w_ih[n]
__global__ void fusew_kernel(const float* __restrict__ w_ih, const float* __restrict__ w_hh,
                             __nv_bfloat16* __restrict__ hi, __nv_bfloat16* __restrict__ lo)
{
    int i = blockIdx.x * blockDim.x + threadIdx.x;
    if (i >= 4*EE*2*EE) return;
    int n = i >> 9, k = i & 511;
    float v = (k < EE) ? w_hh[(long long)n*EE + k] : w_ih[(long long)n*EE + (k-EE)];
    __nv_bfloat16 h, l; split2(v, h, l);
    hi[i] = h; lo[i] = l;
}

__global__ void transpose_kernel(const float* __restrict__ src,
                                 __nv_bfloat16* __restrict__ dh, __nv_bfloat16* __restrict__ dl)
{
    __shared__ float tile[32][33];
    int r0 = blockIdx.x * 32, e0 = blockIdx.y * 32;
    for (int i = threadIdx.y; i < 32; i += 8){
        int r = r0 + i, e = e0 + threadIdx.x;
        tile[i][threadIdx.x] = (r < RR) ? src[(long long)r * EE + e] : 0.f;
    }
    __syncthreads();
    for (int i = threadIdx.y; i < 32; i += 8){
        int e = e0 + i, r = r0 + threadIdx.x;
        __nv_bfloat16 h, l; split2(tile[threadIdx.x][i], h, l);
        dh[(long long)e * RS + r] = h;
        dl[(long long)e * RS + r] = l;
    }
}

__global__ void gather_kernel(const int* __restrict__ bodys, const float* __restrict__ emb_w,
                              __nv_bfloat16* __restrict__ xh, __nv_bfloat16* __restrict__ xl)
{
    int bl = blockIdx.x;
    int r = bodys[bl];
    for (int i = threadIdx.x; i < EE; i += blockDim.x){
        __nv_bfloat16 h, l; split2(emb_w[(long long)r * EE + i], h, l);
        xh[(long long)bl * EE + i] = h;
        xl[(long long)bl * EE + i] = l;
    }
}

__global__ void bsum_kernel(const float* __restrict__ b_ih, const float* __restrict__ b_hh,
                            float* __restrict__ bsum)
{
    int i = threadIdx.x;
    if (i < 4 * EE) bsum[i] = b_ih[i] + b_hh[i];
}

__global__ void zinit_kernel(__nv_bfloat16* __restrict__ hh, __nv_bfloat16* __restrict__ hl,
                             float* __restrict__ c)
{
    int i = blockIdx.x * blockDim.x + threadIdx.x;
    if (i < BB * EE){ hh[i] = __float2bfloat16(0.f); hl[i] = __float2bfloat16(0.f); c[i] = 0.f; }
}

__global__ void lstm_gates(const float* __restrict__ G, __nv_bfloat16* __restrict__ hh,
                           __nv_bfloat16* __restrict__ hl, float* __restrict__ c,
                           float* __restrict__ hid, int t)
{
    int idx = blockIdx.x * blockDim.x + threadIdx.x;
    if (idx >= BB * EE) return;
    int b = idx >> 8, e = idx & 255;
    const float* g = G + (long long)b * (4 * EE);
    float gi = g[e], gf = g[EE + e], gg = g[2*EE + e], go = g[3*EE + e];
    float si = 1.f / (1.f + __expf(-gi));
    float sf = 1.f / (1.f + __expf(-gf));
    float so = 1.f / (1.f + __expf(-go));
    float cn = sf * c[idx] + si * tanhf(gg);
    c[idx] = cn;
    float hn = so * tanhf(cn);
    __nv_bfloat16 hi, lo; split2(hn, hi, lo);
    hh[idx] = hi; hl[idx] = lo;
    hid[((long long)b * LL + t) * EE + e] = hn;
}

// softmax: prob (stride RP1) -> psf hi/lo (stride RS, cols >= RR zeroed), plast[b].
// SMEM-staged: one coalesced fp32 read, one exp pass, paired bf16x2 stores.
__global__ void __launch_bounds__(256) softmax_kernel(
    const float* __restrict__ prob, __nv_bfloat16* __restrict__ ph,
    __nv_bfloat16* __restrict__ pl, float* __restrict__ plast)
{
    __shared__ float sm[RS];
    __shared__ float red[8];
    int b = blockIdx.x, tid = threadIdx.x;
    const float* x = prob + (long long)b * RP1;

    float mx = -1e30f;
    #pragma unroll
    for (int j = 0; j < 40; j++){
        int i = tid + j * 256;
        float t = -1e30f;
        if (i < RP1) t = x[i];
        if (i < RS) sm[i] = t;
        mx = fmaxf(mx, t);
    }
    #pragma unroll
    for (int o = 16; o; o >>= 1) mx = fmaxf(mx, __shfl_xor_sync(0xffffffffu, mx, o));
    if ((tid & 31) == 0) red[tid >> 5] = mx;
    __syncthreads();
    mx = red[0];
    #pragma unroll
    for (int w = 1; w < 8; w++) mx = fmaxf(mx, red[w]);
    __syncthreads();

    float s = 0.f;
    #pragma unroll
    for (int j = 0; j < 40; j++){
        int i = tid + j * 256;
        if (i < RS){
            float e = (i < RP1) ? __expf(sm[i] - mx) : 0.f;
            sm[i] = e; s += e;
        }
    }
    #pragma unroll
    for (int o = 16; o; o >>= 1) s += __shfl_xor_sync(0xffffffffu, s, o);
    __syncthreads();                          // also publishes sm[] exp values
    if ((tid & 31) == 0) red[tid >> 5] = s;
    __syncthreads();
    s = 0.f;
    #pragma unroll
    for (int w = 0; w < 8; w++) s += red[w];
    float inv = 1.f / s;

    __nv_bfloat162* yh2 = (__nv_bfloat162*)(ph + (long long)b * RS);
    __nv_bfloat162* yl2 = (__nv_bfloat162*)(pl + (long long)b * RS);
    const __nv_bfloat16 z = __float2bfloat16(0.f);
    #pragma unroll
    for (int j = 0; j < 20; j++){
        int p = tid + j * 256;
        if (p < RS/2){
            int i0 = 2 * p;
            __nv_bfloat16 h0, l0, h1, l1;
            if (i0 < RR){
                split2(sm[i0] * inv,     h0, l0);
                split2(sm[i0 + 1] * inv, h1, l1);
            } else {
                h0 = l0 = h1 = l1 = z;
                if (i0 == RR) plast[b] = sm[i0] * inv;
            }
            yh2[p] = __nv_bfloat162{h0, h1};
            yl2[p] = __nv_bfloat162{l0, l1};
        }
    }
}

// all svec vectors for iters 1..6: svecs[i-1][e] = fc1_b[e] + dot(fc1_w[e,256:512], emb_w[i+1])
__global__ void svec_all_kernel(const float* __restrict__ fc1_w, const float* __restrict__ fc1_b,
                                const float* __restrict__ emb_w, float* __restrict__ svecs)
{
    __shared__ float er[EE];
    int it = blockIdx.x;               // 0..5 -> iter = it+1, emb row = it+2
    int e = threadIdx.x;
    er[e] = emb_w[(long long)(it + 2) * EE + e];
    __syncthreads();
    const float* w = fc1_w + (long long)e * (2 * EE) + EE;
    float s = fc1_b[e];
    #pragma unroll 8
    for (int k = 0; k < EE; k++) s += w[k] * er[k];
    svecs[(long long)it * EE + e] = s;
}

__global__ void concat_kernel(const float* __restrict__ emb1,
                              const float* __restrict__ emb_w, float* __restrict__ out)
{
    int idx = blockIdx.x * blockDim.x + threadIdx.x;
    if (idx >= BB * 2 * EE) return;
    int b = idx >> 9, e = idx & 511;
    out[idx] = (e < EE) ? emb1[(long long)b * EE + e]
                        : emb_w[(long long)(LL - 1) * EE + (e - EE)];
}

// ------------------------- host launch sequence --------------------------------
template<class T> static T* sym_addr(const void* s){ void* p = nullptr; cudaGetSymbolAddress(&p, s); return (T*)p; }

extern "C" void kernel_launch(void* const* d_in, const int* in_sizes, int n_in,
                              void* d_out, int out_size)
{
    const int*   bodys = (const int*)d_in[0];
    const float* emb_w = (const float*)d_in[1];
    const float* w_ih  = (const float*)d_in[2];
    const float* w_hh  = (const float*)d_in[3];
    const float* b_ih  = (const float*)d_in[4];
    const float* b_hh  = (const float*)d_in[5];
    const float* fc1_w = (const float*)d_in[6];
    const float* fc1_b = (const float*)d_in[7];
    const float* fc2_w = (const float*)d_in[8];
    const float* fc2_b = (const float*)d_in[9];

    float* prob   = (float*)d_out;
    float* outcat = prob + (long long)BB * RP1;

    float* cbuf  = sym_addr<float>(g_c);
    float* G     = sym_addr<float>(g_G);
    float* hid   = sym_addr<float>(g_hid);
    float* emb1  = sym_addr<float>(g_emb1);
    float* part  = sym_addr<float>(g_part);
    float* svecs = sym_addr<float>(g_svecs);
    float* bsum  = sym_addr<float>(g_bsum);
    float* plast = sym_addr<float>(g_plast);

    __nv_bfloat16* xh    = sym_addr<__nv_bfloat16>(g_xh);
    __nv_bfloat16* xl    = sym_addr<__nv_bfloat16>(g_xl);
    __nv_bfloat16* hh    = sym_addr<__nv_bfloat16>(g_hh);
    __nv_bfloat16* hl    = sym_addr<__nv_bfloat16>(g_hl);
    __nv_bfloat16* wfh   = sym_addr<__nv_bfloat16>(g_wfh);
    __nv_bfloat16* wfl   = sym_addr<__nv_bfloat16>(g_wfl);
    __nv_bfloat16* fc1wh = sym_addr<__nv_bfloat16>(g_fc1wh);
    __nv_bfloat16* fc1wl = sym_addr<__nv_bfloat16>(g_fc1wl);
    __nv_bfloat16* fc2wh = sym_addr<__nv_bfloat16>(g_fc2wh);
    __nv_bfloat16* fc2wl = sym_addr<__nv_bfloat16>(g_fc2wl);
    __nv_bfloat16* embTh = sym_addr<__nv_bfloat16>(g_embTh);
    __nv_bfloat16* embTl = sym_addr<__nv_bfloat16>(g_embTl);
    __nv_bfloat16* psfh  = sym_addr<__nv_bfloat16>(g_psfh);
    __nv_bfloat16* psfl  = sym_addr<__nv_bfloat16>(g_psfl);
    __nv_bfloat16* fc1h  = sym_addr<__nv_bfloat16>(g_fc1h);
    __nv_bfloat16* fc1l  = sym_addr<__nv_bfloat16>(g_fc1l);
    __nv_bfloat16* e1h   = sym_addr<__nv_bfloat16>(g_e1h);
    __nv_bfloat16* e1l   = sym_addr<__nv_bfloat16>(g_e1l);

    const __nv_bfloat16* nbf = (const __nv_bfloat16*)nullptr;
    __nv_bfloat16* nbm = (__nv_bfloat16*)nullptr;
    const float* nf = (const float*)nullptr;

    // side stream + fork/join events (created once, before any capture)
    static cudaStream_t s2 = nullptr;
    static cudaEvent_t evG = nullptr, evL = nullptr;
    if (!s2){
        cudaStreamCreateWithFlags(&s2, cudaStreamNonBlocking);
        cudaEventCreateWithFlags(&evG, cudaEventDisableTiming);
        cudaEventCreateWithFlags(&evL, cudaEventDisableTiming);
    }

    cudaFuncSetAttribute(tgemm, cudaFuncAttributeMaxDynamicSharedMemorySize, GSMEM);

    // ---- fork point: gather first (needed by both branches)
    gather_kernel<<<BB*LL, 64>>>(bodys, emb_w, xh, xl);
    cudaEventRecord(evG, 0);
    cudaStreamWaitEvent(s2, evG, 0);

    // ---- side stream: LSTM branch (weights, init, 8 recurrent steps)
    fusew_kernel<<<(4*EE*2*EE + 255)/256, 256, 0, s2>>>(w_ih, w_hh, wfh, wfl);
    bsum_kernel<<<1, 4*EE, 0, s2>>>(b_ih, b_hh, bsum);
    zinit_kernel<<<(BB*EE + 255)/256, 256, 0, s2>>>(hh, hl, cbuf);
    for (int t = 0; t < LL; t++){
        tgemm<<<dim3(8, 8), 512, GSMEM, s2>>>(
            BB, 4*EE, 2*EE,
            hh, hl, EE,
            xh + (long long)t*EE, xl + (long long)t*EE, LL*EE, EE,
            wfh, wfl, 2*EE,
            G, 4*EE, bsum, nf, 0, 0,
            nbm, nbm, 0, (float*)nullptr, 0);
        lstm_gates<<<(BB*EE + 255)/256, 256, 0, s2>>>(G, hh, hl, cbuf, hid, t);
    }
    cudaEventRecord(evL, s2);

    // ---- main stream: prologue for the iteration chain
    conv_kernel<<<(EE*2*EE + 255)/256, 256>>>(fc1_w, fc1wh, fc1wl, EE*2*EE);
    conv_kernel<<<(RP1*EE + 255)/256, 256>>>(fc2_w, fc2wh, fc2wl, RP1*EE);
    transpose_kernel<<<dim3(RS/32, EE/32), dim3(32, 8)>>>(emb_w, embTh, embTl);
    svec_all_kernel<<<6, EE>>>(fc1_w, fc1_b, emb_w, svecs);

    // iteration 0 fc1: emb_concat = x[:,0:2,:] contiguous per row (lda = L*E, K = 512)
    tgemm<<<dim3(2, 8), 512, GSMEM>>>(
        BB, EE, 2*EE, xh, xl, LL*EE, nbf, nbf, 0, 2*EE,
        fc1wh, fc1wl, 2*EE,
        (float*)nullptr, 0, fc1_b, nf, 0, 1,
        fc1h, fc1l, EE, (float*)nullptr, 0);
    tgemm<<<dim3(79, 8), 512, GSMEM>>>(
        BB, RP1, EE, fc1h, fc1l, EE, nbf, nbf, 0, EE,
        fc2wh, fc2wl, EE,
        prob, RP1, fc2_b, nf, 0, 0,
        nbm, nbm, 0, (float*)nullptr, 0);
    softmax_kernel<<<BB, 256>>>(prob, psfh, psfl, plast);

    // iterations 1..6
    for (int i = 1; i < LL - 1; i++){
        // emb_1 partials: psf[:, :R] @ emb_w (split-K = 9 -> 144 CTAs, 1 wave)
        tgemm<<<dim3(2, 8, NSPLIT), 512, GSMEM>>>(
            BB, EE, RS, psfh, psfl, RS, nbf, nbf, 0, RS,
            embTh, embTl, RS,
            (float*)nullptr, 0, nf, nf, 0, 0,
            nbm, nbm, 0, part, KCH);

        if (i == 1) cudaStreamWaitEvent(0, evL, 0);   // join LSTM branch (hid ready)

        reduce_splitk<<<(BB*EE + 255)/256, 256>>>(
            part, emb1, e1h, e1l, hid + (long long)i*EE, plast);

        // fc1: relu(emb_1 @ W1a^T + svec_i)
        tgemm<<<dim3(2, 8), 512, GSMEM>>>(
            BB, EE, EE, e1h, e1l, EE, nbf, nbf, 0, EE,
            fc1wh, fc1wl, 2*EE,
            (float*)nullptr, 0, svecs + (long long)(i-1)*EE, nf, 0, 1,
            fc1h, fc1l, EE, (float*)nullptr, 0);

        // fc2 -> prob
        tgemm<<<dim3(79, 8), 512, GSMEM>>>(
            BB, RP1, EE, fc1h, fc1l, EE, nbf, nbf, 0, EE,
            fc2wh, fc2wl, EE,
            prob, RP1, fc2_b, nf, 0, 0,
            nbm, nbm, 0, (float*)nullptr, 0);

        if (i < LL - 2) softmax_kernel<<<BB, 256>>>(prob, psfh, psfl, plast);
    }

    if (out_size >= BB * RP1 + BB * 2 * EE)
        concat_kernel<<<(BB*2*EE + 255)/256, 256>>>(emb1, emb_w, outcat);
}